// round 2
// baseline (speedup 1.0000x reference)
#include <cuda_runtime.h>
#include <cuda_bf16.h>
#include <math.h>

#define NPIX 4096
#define CCH  512
#define NB   8
#define TOTAL 16777216
#define PI_D 3.14159265358979323846

// ----------------------------- device scratch ------------------------------
__device__ float g_Ak  [512*512];
__device__ float g_AkT [512*512];
__device__ float g_Asp [64*64];
__device__ float g_AspT[64*64];
__device__ float g_W1T [4*512*128];
__device__ float g_W2R [4*9*128*128];
__device__ float g_W3T [4*128*128];
__device__ float g_T [NB*CCH*NPIX];
__device__ float g_D [NB*CCH*NPIX];
__device__ float g_Z [4L*NB*CCH*NPIX];
__device__ float g_H1[4L*NB*128*NPIX];
__device__ float g_H2[4L*NB*128*NPIX];
__device__ float g_L [NB*CCH*NPIX];
__device__ unsigned g_hist1[2048];
__device__ unsigned g_hist2[4*1024];
__device__ unsigned g_hist3[4*1024];
__device__ unsigned g_selBin[8];
__device__ unsigned g_selRank[8];
__device__ unsigned g_thr[4];

// ----------------------------- init kernels --------------------------------
__global__ void k_init_dct() {
    int idx = blockIdx.x * blockDim.x + threadIdx.x;
    if (idx < 512*512) {
        int r = idx >> 9, c = idx & 511;
        double a = (double)r * ((double)c + 0.5) * (PI_D / 512.0);
        float v = (float)(cos(a) * sqrt(2.0 / 512.0));
        if (r == 0) v = (float)(cos(a) * sqrt(1.0 / 512.0));
        g_Ak [r*512 + c] = v;
        g_AkT[c*512 + r] = v;
    }
    if (idx < 64*64) {
        int r = idx >> 6, c = idx & 63;
        double a = (double)r * ((double)c + 0.5) * (PI_D / 64.0);
        float v = (float)(cos(a) * sqrt(2.0 / 64.0));
        if (r == 0) v = (float)(cos(a) * sqrt(1.0 / 64.0));
        g_Asp [r*64 + c] = v;
        g_AspT[c*64 + r] = v;
    }
}

__global__ void k_prep_w(const float* __restrict__ W1, const float* __restrict__ W2,
                         const float* __restrict__ W3) {
    int idx = blockIdx.x * blockDim.x + threadIdx.x;
    if (idx < 4*128*512) {                   // W1[i][o][c] -> W1T[i][c][o]
        int i = idx / (128*512); int rem = idx % (128*512);
        int o = rem / 512, c = rem % 512;
        g_W1T[(i*512 + c)*128 + o] = W1[idx];
    }
    if (idx < 4*128*128*9) {                 // W2[i][o][c][t] -> W2R[i][t][c][o]
        int i = idx / (128*128*9); int rem = idx % (128*128*9);
        int o = rem / (128*9); rem %= (128*9);
        int c = rem / 9, t = rem % 9;
        g_W2R[((i*9 + t)*128 + c)*128 + o] = W2[idx];
    }
    if (idx < 4*128*128) {                   // W3[i][o][c] -> W3T[i][c][o]
        int i = idx / (128*128); int rem = idx % (128*128);
        int o = rem / 128, c = rem % 128;
        g_W3T[(i*128 + c)*128 + o] = W3[idx];
    }
}

// ------------------- per-slice 64x64 two-sided transform --------------------
// result = Amat^T-form @ X @ Amat^T-form; pass Amat=g_AspT for A@X@A^T (fwd),
// Amat=g_Asp for A^T@X@A (inv).
__global__ __launch_bounds__(256) void k_dct2(const float* __restrict__ src,
                                              float* __restrict__ dst,
                                              const float* __restrict__ Amat) {
    __shared__ float sA[64][68];
    __shared__ float sX[64][68];
    int tid = threadIdx.x;
    long base = (long)blockIdx.x * 4096;
    for (int q = tid; q < 4096; q += 256) {
        sA[q >> 6][q & 63] = Amat[q];
        sX[q >> 6][q & 63] = src[base + q];
    }
    __syncthreads();

    int r0 = (tid >> 4) * 4, c0 = (tid & 15) * 4;
    float acc[4][4];
#pragma unroll
    for (int i = 0; i < 4; i++)
#pragma unroll
        for (int j = 0; j < 4; j++) acc[i][j] = 0.f;

#pragma unroll 8
    for (int m = 0; m < 64; m++) {
        float4 a = *(const float4*)&sA[m][r0];
        float4 bvec = *(const float4*)&sX[m][c0];
        float av[4] = {a.x, a.y, a.z, a.w};
        float bv[4] = {bvec.x, bvec.y, bvec.z, bvec.w};
#pragma unroll
        for (int i = 0; i < 4; i++)
#pragma unroll
            for (int j = 0; j < 4; j++) acc[i][j] = fmaf(av[i], bv[j], acc[i][j]);
    }
    __syncthreads();
#pragma unroll
    for (int i = 0; i < 4; i++)
#pragma unroll
        for (int j = 0; j < 4; j++) sX[c0 + j][r0 + i] = acc[i][j];
    __syncthreads();

#pragma unroll
    for (int i = 0; i < 4; i++)
#pragma unroll
        for (int j = 0; j < 4; j++) acc[i][j] = 0.f;
#pragma unroll 8
    for (int n = 0; n < 64; n++) {
        float4 a = *(const float4*)&sX[n][r0];
        float4 bvec = *(const float4*)&sA[n][c0];
        float av[4] = {a.x, a.y, a.z, a.w};
        float bv[4] = {bvec.x, bvec.y, bvec.z, bvec.w};
#pragma unroll
        for (int i = 0; i < 4; i++)
#pragma unroll
            for (int j = 0; j < 4; j++) acc[i][j] = fmaf(av[i], bv[j], acc[i][j]);
    }
#pragma unroll
    for (int i = 0; i < 4; i++) {
        float4 o = make_float4(acc[i][0], acc[i][1], acc[i][2], acc[i][3]);
        *(float4*)&dst[base + (r0 + i)*64 + c0] = o;
    }
}

// --------------------- generic 128x64 fp32 GEMM + epilogue ------------------
__global__ __launch_bounds__(256, 2) void k_gemm(
    const float* __restrict__ ATbase, long aI,
    const float* __restrict__ Bbase, long bI, long bB,
    float* __restrict__ Cbase, long cI, long cB,
    const float* __restrict__ bias, int biasI,
    int K, int Mtot, int NI, int relu)
{
    int zi = blockIdx.z;
    int b = zi / NI, i = zi % NI;
    const float* A = ATbase + (long)i * aI;
    const float* B = Bbase + (long)i * bI + (long)b * bB;
    float* C = Cbase + (long)i * cI + (long)b * cB;
    int m0 = blockIdx.y * 128, n0 = blockIdx.x * 64;

    __shared__ float As[16][132];
    __shared__ float Bs[16][68];
    int tid = threadIdx.x;
    int ar = tid >> 5, ac = (tid & 31) * 4;
    int br = tid >> 4, bc = (tid & 15) * 4;
    int r0 = (tid >> 4) * 8, c00 = (tid & 15) * 4;

    float acc[8][4];
#pragma unroll
    for (int ii = 0; ii < 8; ii++)
#pragma unroll
        for (int jj = 0; jj < 4; jj++) acc[ii][jj] = 0.f;

    for (int k0 = 0; k0 < K; k0 += 16) {
        float4 a0 = *(const float4*)&A[(long)(k0 + ar) * Mtot + m0 + ac];
        float4 a1 = *(const float4*)&A[(long)(k0 + ar + 8) * Mtot + m0 + ac];
        float4 bv = *(const float4*)&B[(long)(k0 + br) * NPIX + n0 + bc];
        __syncthreads();
        *(float4*)&As[ar][ac]     = a0;
        *(float4*)&As[ar + 8][ac] = a1;
        *(float4*)&Bs[br][bc]     = bv;
        __syncthreads();
#pragma unroll
        for (int kk = 0; kk < 16; kk++) {
            float4 x0 = *(const float4*)&As[kk][r0];
            float4 x1 = *(const float4*)&As[kk][r0 + 4];
            float4 y  = *(const float4*)&Bs[kk][c00];
            float av[8] = {x0.x, x0.y, x0.z, x0.w, x1.x, x1.y, x1.z, x1.w};
            float bw[4] = {y.x, y.y, y.z, y.w};
#pragma unroll
            for (int ii = 0; ii < 8; ii++)
#pragma unroll
                for (int jj = 0; jj < 4; jj++)
                    acc[ii][jj] = fmaf(av[ii], bw[jj], acc[ii][jj]);
        }
    }
#pragma unroll
    for (int ii = 0; ii < 8; ii++) {
        int o = m0 + r0 + ii;
        float bvv = bias ? bias[biasI * i + o] : 0.f;
        float4 out;
        out.x = acc[ii][0] + bvv; out.y = acc[ii][1] + bvv;
        out.z = acc[ii][2] + bvv; out.w = acc[ii][3] + bvv;
        if (relu) {
            out.x = fmaxf(out.x, 0.f); out.y = fmaxf(out.y, 0.f);
            out.z = fmaxf(out.z, 0.f); out.w = fmaxf(out.w, 0.f);
        }
        *(float4*)&C[(long)o * NPIX + n0 + c00] = out;
    }
}

// ---------------- masked channel inverse (4 nested masks) -------------------
// Z[i][b][c][p] = sum_k Ak[k][c] * mask_i(D[b][k][p])
__global__ __launch_bounds__(256, 2) void k_gemm_mask(
    const float* __restrict__ ATbase,
    const float* __restrict__ Bbase, long bB,
    float* __restrict__ Cbase, long cI, long cB, int K, int Mtot)
{
    int zi = blockIdx.z;
    int b = zi >> 2, i = zi & 3;
    unsigned thr = g_thr[i];
    const float* A = ATbase;
    const float* B = Bbase + (long)b * bB;
    float* C = Cbase + (long)i * cI + (long)b * cB;
    int m0 = blockIdx.y * 128, n0 = blockIdx.x * 64;

    __shared__ float As[16][132];
    __shared__ float Bs[16][68];
    int tid = threadIdx.x;
    int ar = tid >> 5, ac = (tid & 31) * 4;
    int br = tid >> 4, bc = (tid & 15) * 4;
    int r0 = (tid >> 4) * 8, c00 = (tid & 15) * 4;

    float acc[8][4];
#pragma unroll
    for (int ii = 0; ii < 8; ii++)
#pragma unroll
        for (int jj = 0; jj < 4; jj++) acc[ii][jj] = 0.f;

    for (int k0 = 0; k0 < K; k0 += 16) {
        float4 a0 = *(const float4*)&A[(long)(k0 + ar) * Mtot + m0 + ac];
        float4 a1 = *(const float4*)&A[(long)(k0 + ar + 8) * Mtot + m0 + ac];
        float4 bv = *(const float4*)&B[(long)(k0 + br) * NPIX + n0 + bc];
        bv.x = (__float_as_uint(fabsf(bv.x)) >= thr) ? bv.x : 0.f;
        bv.y = (__float_as_uint(fabsf(bv.y)) >= thr) ? bv.y : 0.f;
        bv.z = (__float_as_uint(fabsf(bv.z)) >= thr) ? bv.z : 0.f;
        bv.w = (__float_as_uint(fabsf(bv.w)) >= thr) ? bv.w : 0.f;
        __syncthreads();
        *(float4*)&As[ar][ac]     = a0;
        *(float4*)&As[ar + 8][ac] = a1;
        *(float4*)&Bs[br][bc]     = bv;
        __syncthreads();
#pragma unroll
        for (int kk = 0; kk < 16; kk++) {
            float4 x0 = *(const float4*)&As[kk][r0];
            float4 x1 = *(const float4*)&As[kk][r0 + 4];
            float4 y  = *(const float4*)&Bs[kk][c00];
            float av[8] = {x0.x, x0.y, x0.z, x0.w, x1.x, x1.y, x1.z, x1.w};
            float bw[4] = {y.x, y.y, y.z, y.w};
#pragma unroll
            for (int ii = 0; ii < 8; ii++)
#pragma unroll
                for (int jj = 0; jj < 4; jj++)
                    acc[ii][jj] = fmaf(av[ii], bw[jj], acc[ii][jj]);
        }
    }
#pragma unroll
    for (int ii = 0; ii < 8; ii++) {
        int o = m0 + r0 + ii;
        float4 out = make_float4(acc[ii][0], acc[ii][1], acc[ii][2], acc[ii][3]);
        *(float4*)&C[(long)o * NPIX + n0 + c00] = out;
    }
}

// --------------------------- dilated 3x3 conv -------------------------------
__global__ __launch_bounds__(256, 2) void k_conv2(const float* __restrict__ b2) {
    int zi = blockIdx.z;
    int b = zi >> 2, i = zi & 3;
    int m = blockIdx.x;                   // output image row
    const float* A = g_W2R + (long)i * 9 * 128 * 128;
    const float* B = g_H1 + ((long)(i*8 + b)) * 128 * 4096;
    float* C = g_H2 + ((long)(i*8 + b)) * 128 * 4096;

    __shared__ float As[16][132];
    __shared__ float Bs[16][68];
    int tid = threadIdx.x;
    int ar = tid >> 5, ac = (tid & 31) * 4;
    int br = tid >> 4, bc = (tid & 15) * 4;
    int r0 = (tid >> 4) * 8, c00 = (tid & 15) * 4;

    float acc[8][4];
#pragma unroll
    for (int ii = 0; ii < 8; ii++)
#pragma unroll
        for (int jj = 0; jj < 4; jj++) acc[ii][jj] = 0.f;

    for (int t = 0; t < 9; t++) {
        int dy = (t / 3) - 1, dx = (t % 3) - 1;
        int mm = m + 2 * dy;
        bool rowok = (mm >= 0 && mm < 64);
        for (int k0 = 0; k0 < 128; k0 += 16) {
            float4 a0 = *(const float4*)&A[(long)(t*128 + k0 + ar) * 128 + ac];
            float4 a1 = *(const float4*)&A[(long)(t*128 + k0 + ar + 8) * 128 + ac];
            float bvv[4];
#pragma unroll
            for (int j = 0; j < 4; j++) {
                int n = bc + j + 2 * dx;
                bvv[j] = (rowok && n >= 0 && n < 64)
                           ? B[(long)(k0 + br) * 4096 + mm * 64 + n] : 0.f;
            }
            __syncthreads();
            *(float4*)&As[ar][ac]     = a0;
            *(float4*)&As[ar + 8][ac] = a1;
            Bs[br][bc] = bvv[0]; Bs[br][bc+1] = bvv[1];
            Bs[br][bc+2] = bvv[2]; Bs[br][bc+3] = bvv[3];
            __syncthreads();
#pragma unroll
            for (int kk = 0; kk < 16; kk++) {
                float4 x0 = *(const float4*)&As[kk][r0];
                float4 x1 = *(const float4*)&As[kk][r0 + 4];
                float4 y  = *(const float4*)&Bs[kk][c00];
                float av[8] = {x0.x, x0.y, x0.z, x0.w, x1.x, x1.y, x1.z, x1.w};
                float bw[4] = {y.x, y.y, y.z, y.w};
#pragma unroll
                for (int ii = 0; ii < 8; ii++)
#pragma unroll
                    for (int jj = 0; jj < 4; jj++)
                        acc[ii][jj] = fmaf(av[ii], bw[jj], acc[ii][jj]);
            }
        }
    }
#pragma unroll
    for (int ii = 0; ii < 8; ii++) {
        int o = r0 + ii;
        float bvv = b2[i * 128 + o];
        float4 out;
        out.x = fmaxf(acc[ii][0] + bvv, 0.f);
        out.y = fmaxf(acc[ii][1] + bvv, 0.f);
        out.z = fmaxf(acc[ii][2] + bvv, 0.f);
        out.w = fmaxf(acc[ii][3] + bvv, 0.f);
        *(float4*)&C[(long)o * 4096 + m * 64 + c00] = out;
    }
}

// --------------------------- radix select -----------------------------------
__global__ void k_hist1() {
    __shared__ unsigned sh[2048];
    for (int q = threadIdx.x; q < 2048; q += 256) sh[q] = 0;
    __syncthreads();
    const float4* D4 = (const float4*)g_D;
    int n4 = TOTAL / 4;
    for (long idx = (long)blockIdx.x * blockDim.x + threadIdx.x; idx < n4;
         idx += (long)gridDim.x * blockDim.x) {
        float4 v = D4[idx];
        atomicAdd(&sh[__float_as_uint(fabsf(v.x)) >> 20], 1u);
        atomicAdd(&sh[__float_as_uint(fabsf(v.y)) >> 20], 1u);
        atomicAdd(&sh[__float_as_uint(fabsf(v.z)) >> 20], 1u);
        atomicAdd(&sh[__float_as_uint(fabsf(v.w)) >> 20], 1u);
    }
    __syncthreads();
    for (int q = threadIdx.x; q < 2048; q += 256)
        if (sh[q]) atomicAdd(&g_hist1[q], sh[q]);
}

__global__ void k_sel1() {
    int i = threadIdx.x;
    if (i >= 4) return;
    unsigned k = (unsigned)(TOTAL >> (2 * (i + 1)));
    unsigned cum = 0;
    for (int bin = 2047; bin >= 0; bin--) {
        unsigned c = g_hist1[bin];
        if (cum + c >= k) { g_selBin[i] = (unsigned)bin; g_selRank[i] = k - cum; return; }
        cum += c;
    }
    g_selBin[i] = 0; g_selRank[i] = 1;
}

__global__ void k_hist2() {
    __shared__ unsigned sh[4096];
    for (int q = threadIdx.x; q < 4096; q += 256) sh[q] = 0;
    __syncthreads();
    unsigned s0 = g_selBin[0], s1 = g_selBin[1], s2 = g_selBin[2], s3 = g_selBin[3];
    const float4* D4 = (const float4*)g_D;
    int n4 = TOTAL / 4;
    for (long idx = (long)blockIdx.x * blockDim.x + threadIdx.x; idx < n4;
         idx += (long)gridDim.x * blockDim.x) {
        float4 v = D4[idx];
        float comps[4] = {v.x, v.y, v.z, v.w};
#pragma unroll
        for (int j = 0; j < 4; j++) {
            unsigned u = __float_as_uint(fabsf(comps[j]));
            unsigned hi = u >> 20, sub = (u >> 10) & 1023;
            if (hi == s0) atomicAdd(&sh[sub], 1u);
            if (hi == s1) atomicAdd(&sh[1024 + sub], 1u);
            if (hi == s2) atomicAdd(&sh[2048 + sub], 1u);
            if (hi == s3) atomicAdd(&sh[3072 + sub], 1u);
        }
    }
    __syncthreads();
    for (int q = threadIdx.x; q < 4096; q += 256)
        if (sh[q]) atomicAdd(&g_hist2[q], sh[q]);
}

__global__ void k_sel2() {
    int i = threadIdx.x;
    if (i >= 4) return;
    unsigned k = g_selRank[i];
    unsigned cum = 0;
    for (int bin = 1023; bin >= 0; bin--) {
        unsigned c = g_hist2[i * 1024 + bin];
        if (cum + c >= k) { g_selBin[4 + i] = (unsigned)bin; g_selRank[4 + i] = k - cum; return; }
        cum += c;
    }
    g_selBin[4 + i] = 0; g_selRank[4 + i] = 1;
}

__global__ void k_hist3() {
    __shared__ unsigned sh[4096];
    for (int q = threadIdx.x; q < 4096; q += 256) sh[q] = 0;
    __syncthreads();
    unsigned t0 = (g_selBin[0] << 10) | g_selBin[4];
    unsigned t1 = (g_selBin[1] << 10) | g_selBin[5];
    unsigned t2 = (g_selBin[2] << 10) | g_selBin[6];
    unsigned t3 = (g_selBin[3] << 10) | g_selBin[7];
    const float4* D4 = (const float4*)g_D;
    int n4 = TOTAL / 4;
    for (long idx = (long)blockIdx.x * blockDim.x + threadIdx.x; idx < n4;
         idx += (long)gridDim.x * blockDim.x) {
        float4 v = D4[idx];
        float comps[4] = {v.x, v.y, v.z, v.w};
#pragma unroll
        for (int j = 0; j < 4; j++) {
            unsigned u = __float_as_uint(fabsf(comps[j]));
            unsigned hi = u >> 10, lo = u & 1023;
            if (hi == t0) atomicAdd(&sh[lo], 1u);
            if (hi == t1) atomicAdd(&sh[1024 + lo], 1u);
            if (hi == t2) atomicAdd(&sh[2048 + lo], 1u);
            if (hi == t3) atomicAdd(&sh[3072 + lo], 1u);
        }
    }
    __syncthreads();
    for (int q = threadIdx.x; q < 4096; q += 256)
        if (sh[q]) atomicAdd(&g_hist3[q], sh[q]);
}

__global__ void k_sel3() {
    int i = threadIdx.x;
    if (i >= 4) return;
    unsigned k = g_selRank[4 + i];
    unsigned cum = 0;
    for (int bin = 1023; bin >= 0; bin--) {
        unsigned c = g_hist3[i * 1024 + bin];
        if (cum + c >= k) {
            g_thr[i] = (g_selBin[i] << 20) | (g_selBin[4 + i] << 10) | (unsigned)bin;
            return;
        }
        cum += c;
    }
    g_thr[i] = (g_selBin[i] << 20) | (g_selBin[4 + i] << 10);
}

// ------------------------- softmax + residual gate --------------------------
__global__ __launch_bounds__(128) void k_softmax(const float* __restrict__ x,
                                                 float* __restrict__ out) {
    int b = blockIdx.y;
    int p = blockIdx.x * 128 + threadIdx.x;
    const float* Lp = g_L + (long)b * 512 * 4096 + p;
    float mx = 0.f;
#pragma unroll 8
    for (int c = 0; c < 512; c++) mx = fmaxf(mx, Lp[(long)c * 4096]);
    float s = 0.f;
#pragma unroll 8
    for (int c = 0; c < 512; c++) s += __expf(Lp[(long)c * 4096] - mx);
    float inv = 1.f / s;
    const float* xp = x + (long)b * 512 * 4096 + p;
    float* op = out + (long)b * 512 * 4096 + p;
#pragma unroll 8
    for (int c = 0; c < 512; c++) {
        float w = __expf(Lp[(long)c * 4096] - mx) * inv;
        float xv = xp[(long)c * 4096];
        op[(long)c * 4096] = fmaf(xv, w, xv);
    }
}

// ------------------------------- launcher -----------------------------------
extern "C" void kernel_launch(void* const* d_in, const int* in_sizes, int n_in,
                              void* d_out, int out_size) {
    (void)in_sizes; (void)n_in; (void)out_size;
    const float* x  = (const float*)d_in[0];
    const float* W1 = (const float*)d_in[1];
    const float* b1 = (const float*)d_in[2];
    const float* W2 = (const float*)d_in[3];
    const float* b2 = (const float*)d_in[4];
    const float* W3 = (const float*)d_in[5];
    const float* b3 = (const float*)d_in[6];
    float* out = (float*)d_out;

    float *pAk, *pAkT, *pAsp, *pAspT, *pW1T, *pW3T;
    float *pT, *pD, *pZ, *pH1, *pH2, *pL;
    unsigned *ph1, *ph2, *ph3;
    cudaGetSymbolAddress((void**)&pAk,  g_Ak);
    cudaGetSymbolAddress((void**)&pAkT, g_AkT);
    cudaGetSymbolAddress((void**)&pAsp, g_Asp);
    cudaGetSymbolAddress((void**)&pAspT,g_AspT);
    cudaGetSymbolAddress((void**)&pW1T, g_W1T);
    cudaGetSymbolAddress((void**)&pW3T, g_W3T);
    cudaGetSymbolAddress((void**)&pT,  g_T);
    cudaGetSymbolAddress((void**)&pD,  g_D);
    cudaGetSymbolAddress((void**)&pZ,  g_Z);
    cudaGetSymbolAddress((void**)&pH1, g_H1);
    cudaGetSymbolAddress((void**)&pH2, g_H2);
    cudaGetSymbolAddress((void**)&pL,  g_L);
    cudaGetSymbolAddress((void**)&ph1, g_hist1);
    cudaGetSymbolAddress((void**)&ph2, g_hist2);
    cudaGetSymbolAddress((void**)&ph3, g_hist3);

    k_init_dct<<<1024, 256>>>();
    k_prep_w<<<2304, 256>>>(W1, W2, W3);

    // forward spatial DCT: T = Asp @ X @ Asp^T per (b,c) slice
    k_dct2<<<4096, 256>>>(x, pT, pAspT);

    // forward channel DCT: D[b] = Ak @ T[b]
    k_gemm<<<dim3(64, 4, 8), 256>>>(pAkT, 0, pT, 0, (long)CCH*NPIX,
                                    pD, 0, (long)CCH*NPIX,
                                    nullptr, 0, 512, 512, 1, 0);

    // radix select thresholds (bit-exact kth largest of |D|)
    cudaMemsetAsync(ph1, 0, 2048 * sizeof(unsigned));
    cudaMemsetAsync(ph2, 0, 4096 * sizeof(unsigned));
    cudaMemsetAsync(ph3, 0, 4096 * sizeof(unsigned));
    k_hist1<<<2048, 256>>>();
    k_sel1<<<1, 4>>>();
    k_hist2<<<2048, 256>>>();
    k_sel2<<<1, 4>>>();
    k_hist3<<<2048, 256>>>();
    k_sel3<<<1, 4>>>();

    // masked channel inverse: Z[i][b] = Ak^T @ mask_i(D[b])
    k_gemm_mask<<<dim3(64, 4, 32), 256>>>(pAk, pD, (long)CCH*NPIX,
                                          pZ, (long)NB*CCH*NPIX, (long)CCH*NPIX,
                                          512, 512);

    // inverse spatial DCT in place: Z = Asp^T @ Z @ Asp per slice
    k_dct2<<<16384, 256>>>(pZ, pZ, pAsp);

    // conv1: 1x1 512->128 + bias + relu
    k_gemm<<<dim3(64, 1, 32), 256>>>(pW1T, (long)512*128,
                                     pZ, (long)NB*CCH*NPIX, (long)CCH*NPIX,
                                     pH1, (long)NB*128*NPIX, (long)128*NPIX,
                                     b1, 128, 512, 128, 4, 1);

    // conv2: 3x3 dilation-2 128->128 + bias + relu
    k_conv2<<<dim3(64, 1, 32), 256>>>(b2);

    // conv3: 1x1 128->128 + bias + relu -> logits
    k_gemm<<<dim3(64, 1, 32), 256>>>(pW3T, (long)128*128,
                                     pH2, (long)NB*128*NPIX, (long)128*NPIX,
                                     pL, (long)128*NPIX, (long)CCH*NPIX,
                                     b3, 128, 128, 128, 4, 1);

    // softmax over 512 channels + residual gate
    k_softmax<<<dim3(32, 8), 128>>>(x, out);
}

// round 5
// speedup vs baseline: 1.4234x; 1.4234x over previous
#include <cuda_runtime.h>
#include <cuda_bf16.h>
#include <math.h>
#include <stdint.h>

#define NPIX 4096
#define CCH  512
#define NB   8
#define TOTAL 16777216
#define PI_D 3.14159265358979323846

// ----------------------------- device scratch ------------------------------
__device__ float g_Ak  [512*512];
__device__ float g_AkT [512*512];
__device__ float g_Asp [64*64];
__device__ float g_AspT[64*64];
__device__ float g_W1T [4*512*128];
__device__ float g_W2R [4*9*128*128];
__device__ float g_W3T [4*128*128];
__device__ __nv_bfloat16 g_AkTb[512*512];           // [c][k] bf16
__device__ __nv_bfloat16 g_Dt[(size_t)NB*NPIX*CCH]; // [b][p][k] bf16
__device__ float g_T [NB*CCH*NPIX];
__device__ float g_D [NB*CCH*NPIX];
__device__ float g_Z [4L*NB*CCH*NPIX];
__device__ float g_H1[4L*NB*128*NPIX];
__device__ float g_H2[4L*NB*128*NPIX];
__device__ float g_L [NB*CCH*NPIX];
__device__ unsigned g_hist1[2048];
__device__ unsigned g_hist2[4*1024];
__device__ unsigned g_hist3[4*1024];
__device__ unsigned g_selBin[8];
__device__ unsigned g_selRank[8];
__device__ unsigned g_thr[4];

// ----------------------------- init kernels --------------------------------
__global__ void k_init_dct() {
    int idx = blockIdx.x * blockDim.x + threadIdx.x;
    if (idx < 512*512) {
        int r = idx >> 9, c = idx & 511;
        double a = (double)r * ((double)c + 0.5) * (PI_D / 512.0);
        float v = (float)(cos(a) * sqrt(2.0 / 512.0));
        if (r == 0) v = (float)(cos(a) * sqrt(1.0 / 512.0));
        g_Ak [r*512 + c] = v;
        g_AkT[c*512 + r] = v;
    }
    if (idx < 64*64) {
        int r = idx >> 6, c = idx & 63;
        double a = (double)r * ((double)c + 0.5) * (PI_D / 64.0);
        float v = (float)(cos(a) * sqrt(2.0 / 64.0));
        if (r == 0) v = (float)(cos(a) * sqrt(1.0 / 64.0));
        g_Asp [r*64 + c] = v;
        g_AspT[c*64 + r] = v;
    }
}

__global__ void k_prep_akb() {
    int idx = blockIdx.x * blockDim.x + threadIdx.x;
    if (idx < 512*512) g_AkTb[idx] = __float2bfloat16(g_AkT[idx]);
}

__global__ void k_prep_w(const float* __restrict__ W1, const float* __restrict__ W2,
                         const float* __restrict__ W3) {
    int idx = blockIdx.x * blockDim.x + threadIdx.x;
    if (idx < 4*128*512) {
        int i = idx / (128*512); int rem = idx % (128*512);
        int o = rem / 512, c = rem % 512;
        g_W1T[(i*512 + c)*128 + o] = W1[idx];
    }
    if (idx < 4*128*128*9) {
        int i = idx / (128*128*9); int rem = idx % (128*128*9);
        int o = rem / (128*9); rem %= (128*9);
        int c = rem / 9, t = rem % 9;
        g_W2R[((i*9 + t)*128 + c)*128 + o] = W2[idx];
    }
    if (idx < 4*128*128) {
        int i = idx / (128*128); int rem = idx % (128*128);
        int o = rem / 128, c = rem % 128;
        g_W3T[(i*128 + c)*128 + o] = W3[idx];
    }
}

// ------------------- per-slice 64x64 two-sided transform --------------------
__global__ __launch_bounds__(256) void k_dct2(const float* __restrict__ src,
                                              float* __restrict__ dst,
                                              const float* __restrict__ Amat) {
    __shared__ float sA[64][68];
    __shared__ float sX[64][68];
    int tid = threadIdx.x;
    long base = (long)blockIdx.x * 4096;
    for (int q = tid; q < 4096; q += 256) {
        sA[q >> 6][q & 63] = Amat[q];
        sX[q >> 6][q & 63] = src[base + q];
    }
    __syncthreads();

    int r0 = (tid >> 4) * 4, c0 = (tid & 15) * 4;
    float acc[4][4];
#pragma unroll
    for (int i = 0; i < 4; i++)
#pragma unroll
        for (int j = 0; j < 4; j++) acc[i][j] = 0.f;

#pragma unroll 8
    for (int m = 0; m < 64; m++) {
        float4 a = *(const float4*)&sA[m][r0];
        float4 bvec = *(const float4*)&sX[m][c0];
        float av[4] = {a.x, a.y, a.z, a.w};
        float bv[4] = {bvec.x, bvec.y, bvec.z, bvec.w};
#pragma unroll
        for (int i = 0; i < 4; i++)
#pragma unroll
            for (int j = 0; j < 4; j++) acc[i][j] = fmaf(av[i], bv[j], acc[i][j]);
    }
    __syncthreads();
#pragma unroll
    for (int i = 0; i < 4; i++)
#pragma unroll
        for (int j = 0; j < 4; j++) sX[c0 + j][r0 + i] = acc[i][j];
    __syncthreads();

#pragma unroll
    for (int i = 0; i < 4; i++)
#pragma unroll
        for (int j = 0; j < 4; j++) acc[i][j] = 0.f;
#pragma unroll 8
    for (int n = 0; n < 64; n++) {
        float4 a = *(const float4*)&sX[n][r0];
        float4 bvec = *(const float4*)&sA[n][c0];
        float av[4] = {a.x, a.y, a.z, a.w};
        float bv[4] = {bvec.x, bvec.y, bvec.z, bvec.w};
#pragma unroll
        for (int i = 0; i < 4; i++)
#pragma unroll
            for (int j = 0; j < 4; j++) acc[i][j] = fmaf(av[i], bv[j], acc[i][j]);
    }
#pragma unroll
    for (int i = 0; i < 4; i++) {
        float4 o = make_float4(acc[i][0], acc[i][1], acc[i][2], acc[i][3]);
        *(float4*)&dst[base + (r0 + i)*64 + c0] = o;
    }
}

// --------------------- generic 128x64 fp32 GEMM + epilogue ------------------
__global__ __launch_bounds__(256, 2) void k_gemm(
    const float* __restrict__ ATbase, long aI,
    const float* __restrict__ Bbase, long bI, long bB,
    float* __restrict__ Cbase, long cI, long cB,
    const float* __restrict__ bias, int biasI,
    int K, int Mtot, int NI, int relu)
{
    int zi = blockIdx.z;
    int b = zi / NI, i = zi % NI;
    const float* A = ATbase + (long)i * aI;
    const float* B = Bbase + (long)i * bI + (long)b * bB;
    float* C = Cbase + (long)i * cI + (long)b * cB;
    int m0 = blockIdx.y * 128, n0 = blockIdx.x * 64;

    __shared__ float As[16][132];
    __shared__ float Bs[16][68];
    int tid = threadIdx.x;
    int ar = tid >> 5, ac = (tid & 31) * 4;
    int br = tid >> 4, bc = (tid & 15) * 4;
    int r0 = (tid >> 4) * 8, c00 = (tid & 15) * 4;

    float acc[8][4];
#pragma unroll
    for (int ii = 0; ii < 8; ii++)
#pragma unroll
        for (int jj = 0; jj < 4; jj++) acc[ii][jj] = 0.f;

    for (int k0 = 0; k0 < K; k0 += 16) {
        float4 a0 = *(const float4*)&A[(long)(k0 + ar) * Mtot + m0 + ac];
        float4 a1 = *(const float4*)&A[(long)(k0 + ar + 8) * Mtot + m0 + ac];
        float4 bv = *(const float4*)&B[(long)(k0 + br) * NPIX + n0 + bc];
        __syncthreads();
        *(float4*)&As[ar][ac]     = a0;
        *(float4*)&As[ar + 8][ac] = a1;
        *(float4*)&Bs[br][bc]     = bv;
        __syncthreads();
#pragma unroll
        for (int kk = 0; kk < 16; kk++) {
            float4 x0 = *(const float4*)&As[kk][r0];
            float4 x1 = *(const float4*)&As[kk][r0 + 4];
            float4 y  = *(const float4*)&Bs[kk][c00];
            float av[8] = {x0.x, x0.y, x0.z, x0.w, x1.x, x1.y, x1.z, x1.w};
            float bw[4] = {y.x, y.y, y.z, y.w};
#pragma unroll
            for (int ii = 0; ii < 8; ii++)
#pragma unroll
                for (int jj = 0; jj < 4; jj++)
                    acc[ii][jj] = fmaf(av[ii], bw[jj], acc[ii][jj]);
        }
    }
#pragma unroll
    for (int ii = 0; ii < 8; ii++) {
        int o = m0 + r0 + ii;
        float bvv = bias ? bias[biasI * i + o] : 0.f;
        float4 out;
        out.x = acc[ii][0] + bvv; out.y = acc[ii][1] + bvv;
        out.z = acc[ii][2] + bvv; out.w = acc[ii][3] + bvv;
        if (relu) {
            out.x = fmaxf(out.x, 0.f); out.y = fmaxf(out.y, 0.f);
            out.z = fmaxf(out.z, 0.f); out.w = fmaxf(out.w, 0.f);
        }
        *(float4*)&C[(long)o * NPIX + n0 + c00] = out;
    }
}

// -------------------- transpose D [k][p] -> Dt bf16 [p][k] ------------------
__global__ __launch_bounds__(256) void k_trans() {
    __shared__ float st[64][65];
    int p0 = blockIdx.x * 64, k0 = blockIdx.y * 64, b = blockIdx.z;
    const float* D = g_D + (size_t)b * CCH * NPIX;
    int tid = threadIdx.x;
#pragma unroll
    for (int ps = 0; ps < 16; ps++) {
        int idx = ps * 256 + tid;
        int r = idx >> 6, c = idx & 63;
        st[r][c] = D[(size_t)(k0 + r) * 4096 + p0 + c];
    }
    __syncthreads();
    __nv_bfloat16* Dt = g_Dt + (size_t)b * NPIX * CCH;
#pragma unroll
    for (int ps = 0; ps < 8; ps++) {
        int idx = ps * 256 + tid;
        int rr = idx >> 5, cc = idx & 31;
        __nv_bfloat162 v;
        v.x = __float2bfloat16(st[2*cc][rr]);
        v.y = __float2bfloat16(st[2*cc + 1][rr]);
        *(__nv_bfloat162*)&Dt[(size_t)(p0 + rr) * 512 + k0 + 2*cc] = v;
    }
}

// ------------- masked channel inverse via mma.sync (bf16 HMMA) --------------
// Z[i][b][c][p] = sum_k AkT[c][k] * mask_i(Dt[b][p][k])
#define LDB 72   // smem row stride in bf16 (64 data + 8 pad)

__device__ __forceinline__ unsigned mask2(unsigned w, unsigned thrb) {
    unsigned lo = w & 0x7FFFu, hi = (w >> 16) & 0x7FFFu;
    unsigned r = w;
    if (lo < thrb) r &= 0xFFFF0000u;
    if (hi < thrb) r &= 0x0000FFFFu;
    return r;
}

__device__ __forceinline__ uint32_t smem_u32(const void* p) {
    uint32_t a;
    asm("{ .reg .u64 t; cvta.to.shared.u64 t, %1; cvt.u32.u64 %0, t; }"
        : "=r"(a) : "l"(p));
    return a;
}

__global__ __launch_bounds__(256, 2) void k_inv_mma() {
    __shared__ __nv_bfloat16 sA[128 * LDB];
    __shared__ __nv_bfloat16 sB[128 * LDB];
    int tid = threadIdx.x, wid = tid >> 5, lane = tid & 31;
    int z = blockIdx.z;
    int b = z >> 2, i = z & 3;
    int c0 = blockIdx.y * 128, n0 = blockIdx.x * 128;
    unsigned thr = g_thr[i];
    unsigned thrb = (thr + 0x7FFFu + ((thr >> 16) & 1u)) >> 16;  // RNE fp32->bf16

    const uint4* Ag = (const uint4*)g_AkTb;
    const uint4* Bg = (const uint4*)(g_Dt + (size_t)b * NPIX * CCH);

    int wm = wid & 1;        // 0..1 -> 64-row half of M
    int wn = wid >> 1;       // 0..3 -> 32-col quarter of N

    float acc[4][4][4];
#pragma unroll
    for (int mi = 0; mi < 4; mi++)
#pragma unroll
        for (int ni = 0; ni < 4; ni++)
#pragma unroll
            for (int q = 0; q < 4; q++) acc[mi][ni][q] = 0.f;

    // ldmatrix source addresses (fixed per thread, chunk-invariant)
    uint32_t aAddr[4], bAddr[4];
#pragma unroll
    for (int mi = 0; mi < 4; mi++) {
        int row = wm * 64 + mi * 16 + (lane & 15);
        int col = (lane >> 4) << 3;
        aAddr[mi] = smem_u32(&sA[row * LDB + col]);
    }
#pragma unroll
    for (int ni = 0; ni < 4; ni++) {
        int row = wn * 32 + ni * 8 + (lane & 7);
        int col = ((lane >> 3) & 1) << 3;
        bAddr[ni] = smem_u32(&sB[row * LDB + col]);
    }

    for (int ch = 0; ch < 8; ch++) {
        int k0 = ch * 64;
        // load 128x64 bf16 tiles (A plain, B masked), 4 uint4 per thread each
        uint4 av[4], bv[4];
#pragma unroll
        for (int ps = 0; ps < 4; ps++) {
            int idx = ps * 256 + tid;
            int row = idx >> 3, slot = idx & 7;
            av[ps] = Ag[(((size_t)(c0 + row) * 512 + k0) >> 3) + slot];
            bv[ps] = Bg[(((size_t)(n0 + row) * 512 + k0) >> 3) + slot];
            bv[ps].x = mask2(bv[ps].x, thrb);
            bv[ps].y = mask2(bv[ps].y, thrb);
            bv[ps].z = mask2(bv[ps].z, thrb);
            bv[ps].w = mask2(bv[ps].w, thrb);
        }
        __syncthreads();
#pragma unroll
        for (int ps = 0; ps < 4; ps++) {
            int idx = ps * 256 + tid;
            int row = idx >> 3, slot = idx & 7;
            *(uint4*)&sA[row * LDB + slot * 8] = av[ps];
            *(uint4*)&sB[row * LDB + slot * 8] = bv[ps];
        }
        __syncthreads();

#pragma unroll
        for (int ks = 0; ks < 4; ks++) {
            uint32_t af[4][4], bf[4][2];
#pragma unroll
            for (int mi = 0; mi < 4; mi++) {
                asm volatile(
                    "ldmatrix.sync.aligned.m8n8.x4.shared.b16 {%0,%1,%2,%3}, [%4];"
                    : "=r"(af[mi][0]), "=r"(af[mi][1]), "=r"(af[mi][2]), "=r"(af[mi][3])
                    : "r"(aAddr[mi] + ks * 32));
            }
#pragma unroll
            for (int ni = 0; ni < 4; ni++) {
                asm volatile(
                    "ldmatrix.sync.aligned.m8n8.x2.shared.b16 {%0,%1}, [%2];"
                    : "=r"(bf[ni][0]), "=r"(bf[ni][1])
                    : "r"(bAddr[ni] + ks * 32));
            }
#pragma unroll
            for (int mi = 0; mi < 4; mi++)
#pragma unroll
                for (int ni = 0; ni < 4; ni++) {
                    asm volatile(
                        "mma.sync.aligned.m16n8k16.row.col.f32.bf16.bf16.f32 "
                        "{%0,%1,%2,%3}, {%4,%5,%6,%7}, {%8,%9}, {%0,%1,%2,%3};"
                        : "+f"(acc[mi][ni][0]), "+f"(acc[mi][ni][1]),
                          "+f"(acc[mi][ni][2]), "+f"(acc[mi][ni][3])
                        : "r"(af[mi][0]), "r"(af[mi][1]), "r"(af[mi][2]), "r"(af[mi][3]),
                          "r"(bf[ni][0]), "r"(bf[ni][1]));
                }
        }
    }

    // epilogue: C[c][p], c row-major
    float* C = g_Z + ((size_t)i * NB + b) * CCH * NPIX;
    int gq = lane >> 2, tq = lane & 3;
#pragma unroll
    for (int mi = 0; mi < 4; mi++) {
        int row = c0 + wm * 64 + mi * 16 + gq;
#pragma unroll
        for (int ni = 0; ni < 4; ni++) {
            int col = n0 + wn * 32 + ni * 8 + tq * 2;
            *(float2*)&C[(size_t)row * 4096 + col] =
                make_float2(acc[mi][ni][0], acc[mi][ni][1]);
            *(float2*)&C[(size_t)(row + 8) * 4096 + col] =
                make_float2(acc[mi][ni][2], acc[mi][ni][3]);
        }
    }
}

// --------------------------- dilated 3x3 conv -------------------------------
__global__ __launch_bounds__(256, 2) void k_conv2(const float* __restrict__ b2) {
    int zi = blockIdx.z;
    int b = zi >> 2, i = zi & 3;
    int m = blockIdx.x;
    const float* A = g_W2R + (long)i * 9 * 128 * 128;
    const float* B = g_H1 + ((long)(i*8 + b)) * 128 * 4096;
    float* C = g_H2 + ((long)(i*8 + b)) * 128 * 4096;

    __shared__ float As[16][132];
    __shared__ float Bs[16][68];
    int tid = threadIdx.x;
    int ar = tid >> 5, ac = (tid & 31) * 4;
    int br = tid >> 4, bc = (tid & 15) * 4;
    int r0 = (tid >> 4) * 8, c00 = (tid & 15) * 4;

    float acc[8][4];
#pragma unroll
    for (int ii = 0; ii < 8; ii++)
#pragma unroll
        for (int jj = 0; jj < 4; jj++) acc[ii][jj] = 0.f;

    for (int t = 0; t < 9; t++) {
        int dy = (t / 3) - 1, dx = (t % 3) - 1;
        int mm = m + 2 * dy;
        bool rowok = (mm >= 0 && mm < 64);
        for (int k0 = 0; k0 < 128; k0 += 16) {
            float4 a0 = *(const float4*)&A[(long)(t*128 + k0 + ar) * 128 + ac];
            float4 a1 = *(const float4*)&A[(long)(t*128 + k0 + ar + 8) * 128 + ac];
            float bvv[4];
#pragma unroll
            for (int j = 0; j < 4; j++) {
                int n = bc + j + 2 * dx;
                bvv[j] = (rowok && n >= 0 && n < 64)
                           ? B[(long)(k0 + br) * 4096 + mm * 64 + n] : 0.f;
            }
            __syncthreads();
            *(float4*)&As[ar][ac]     = a0;
            *(float4*)&As[ar + 8][ac] = a1;
            Bs[br][bc] = bvv[0]; Bs[br][bc+1] = bvv[1];
            Bs[br][bc+2] = bvv[2]; Bs[br][bc+3] = bvv[3];
            __syncthreads();
#pragma unroll
            for (int kk = 0; kk < 16; kk++) {
                float4 x0 = *(const float4*)&As[kk][r0];
                float4 x1 = *(const float4*)&As[kk][r0 + 4];
                float4 y  = *(const float4*)&Bs[kk][c00];
                float av[8] = {x0.x, x0.y, x0.z, x0.w, x1.x, x1.y, x1.z, x1.w};
                float bw[4] = {y.x, y.y, y.z, y.w};
#pragma unroll
                for (int ii = 0; ii < 8; ii++)
#pragma unroll
                    for (int jj = 0; jj < 4; jj++)
                        acc[ii][jj] = fmaf(av[ii], bw[jj], acc[ii][jj]);
            }
        }
    }
#pragma unroll
    for (int ii = 0; ii < 8; ii++) {
        int o = r0 + ii;
        float bvv = b2[i * 128 + o];
        float4 out;
        out.x = fmaxf(acc[ii][0] + bvv, 0.f);
        out.y = fmaxf(acc[ii][1] + bvv, 0.f);
        out.z = fmaxf(acc[ii][2] + bvv, 0.f);
        out.w = fmaxf(acc[ii][3] + bvv, 0.f);
        *(float4*)&C[(long)o * 4096 + m * 64 + c00] = out;
    }
}

// --------------------------- radix select -----------------------------------
__global__ void k_hist1() {
    __shared__ unsigned sh[2048];
    for (int q = threadIdx.x; q < 2048; q += 256) sh[q] = 0;
    __syncthreads();
    const float4* D4 = (const float4*)g_D;
    int n4 = TOTAL / 4;
    for (long idx = (long)blockIdx.x * blockDim.x + threadIdx.x; idx < n4;
         idx += (long)gridDim.x * blockDim.x) {
        float4 v = D4[idx];
        atomicAdd(&sh[__float_as_uint(fabsf(v.x)) >> 20], 1u);
        atomicAdd(&sh[__float_as_uint(fabsf(v.y)) >> 20], 1u);
        atomicAdd(&sh[__float_as_uint(fabsf(v.z)) >> 20], 1u);
        atomicAdd(&sh[__float_as_uint(fabsf(v.w)) >> 20], 1u);
    }
    __syncthreads();
    for (int q = threadIdx.x; q < 2048; q += 256)
        if (sh[q]) atomicAdd(&g_hist1[q], sh[q]);
}

__global__ void k_sel1() {
    int i = threadIdx.x;
    if (i >= 4) return;
    unsigned k = (unsigned)(TOTAL >> (2 * (i + 1)));
    unsigned cum = 0;
    for (int bin = 2047; bin >= 0; bin--) {
        unsigned c = g_hist1[bin];
        if (cum + c >= k) { g_selBin[i] = (unsigned)bin; g_selRank[i] = k - cum; return; }
        cum += c;
    }
    g_selBin[i] = 0; g_selRank[i] = 1;
}

__global__ void k_hist2() {
    __shared__ unsigned sh[4096];
    for (int q = threadIdx.x; q < 4096; q += 256) sh[q] = 0;
    __syncthreads();
    unsigned s0 = g_selBin[0], s1 = g_selBin[1], s2 = g_selBin[2], s3 = g_selBin[3];
    const float4* D4 = (const float4*)g_D;
    int n4 = TOTAL / 4;
    for (long idx = (long)blockIdx.x * blockDim.x + threadIdx.x; idx < n4;
         idx += (long)gridDim.x * blockDim.x) {
        float4 v = D4[idx];
        float comps[4] = {v.x, v.y, v.z, v.w};
#pragma unroll
        for (int j = 0; j < 4; j++) {
            unsigned u = __float_as_uint(fabsf(comps[j]));
            unsigned hi = u >> 20, sub = (u >> 10) & 1023;
            if (hi == s0) atomicAdd(&sh[sub], 1u);
            if (hi == s1) atomicAdd(&sh[1024 + sub], 1u);
            if (hi == s2) atomicAdd(&sh[2048 + sub], 1u);
            if (hi == s3) atomicAdd(&sh[3072 + sub], 1u);
        }
    }
    __syncthreads();
    for (int q = threadIdx.x; q < 4096; q += 256)
        if (sh[q]) atomicAdd(&g_hist2[q], sh[q]);
}

__global__ void k_sel2() {
    int i = threadIdx.x;
    if (i >= 4) return;
    unsigned k = g_selRank[i];
    unsigned cum = 0;
    for (int bin = 1023; bin >= 0; bin--) {
        unsigned c = g_hist2[i * 1024 + bin];
        if (cum + c >= k) { g_selBin[4 + i] = (unsigned)bin; g_selRank[4 + i] = k - cum; return; }
        cum += c;
    }
    g_selBin[4 + i] = 0; g_selRank[4 + i] = 1;
}

__global__ void k_hist3() {
    __shared__ unsigned sh[4096];
    for (int q = threadIdx.x; q < 4096; q += 256) sh[q] = 0;
    __syncthreads();
    unsigned t0 = (g_selBin[0] << 10) | g_selBin[4];
    unsigned t1 = (g_selBin[1] << 10) | g_selBin[5];
    unsigned t2 = (g_selBin[2] << 10) | g_selBin[6];
    unsigned t3 = (g_selBin[3] << 10) | g_selBin[7];
    const float4* D4 = (const float4*)g_D;
    int n4 = TOTAL / 4;
    for (long idx = (long)blockIdx.x * blockDim.x + threadIdx.x; idx < n4;
         idx += (long)gridDim.x * blockDim.x) {
        float4 v = D4[idx];
        float comps[4] = {v.x, v.y, v.z, v.w};
#pragma unroll
        for (int j = 0; j < 4; j++) {
            unsigned u = __float_as_uint(fabsf(comps[j]));
            unsigned hi = u >> 10, lo = u & 1023;
            if (hi == t0) atomicAdd(&sh[lo], 1u);
            if (hi == t1) atomicAdd(&sh[1024 + lo], 1u);
            if (hi == t2) atomicAdd(&sh[2048 + lo], 1u);
            if (hi == t3) atomicAdd(&sh[3072 + lo], 1u);
        }
    }
    __syncthreads();
    for (int q = threadIdx.x; q < 4096; q += 256)
        if (sh[q]) atomicAdd(&g_hist3[q], sh[q]);
}

__global__ void k_sel3() {
    int i = threadIdx.x;
    if (i >= 4) return;
    unsigned k = g_selRank[4 + i];
    unsigned cum = 0;
    for (int bin = 1023; bin >= 0; bin--) {
        unsigned c = g_hist3[i * 1024 + bin];
        if (cum + c >= k) {
            g_thr[i] = (g_selBin[i] << 20) | (g_selBin[4 + i] << 10) | (unsigned)bin;
            return;
        }
        cum += c;
    }
    g_thr[i] = (g_selBin[i] << 20) | (g_selBin[4 + i] << 10);
}

// ------------------------- softmax + residual gate --------------------------
__global__ __launch_bounds__(128) void k_softmax(const float* __restrict__ x,
                                                 float* __restrict__ out) {
    int b = blockIdx.y;
    int p = blockIdx.x * 128 + threadIdx.x;
    const float* Lp = g_L + (long)b * 512 * 4096 + p;
    float mx = 0.f;
#pragma unroll 8
    for (int c = 0; c < 512; c++) mx = fmaxf(mx, Lp[(long)c * 4096]);
    float s = 0.f;
#pragma unroll 8
    for (int c = 0; c < 512; c++) s += __expf(Lp[(long)c * 4096] - mx);
    float inv = 1.f / s;
    const float* xp = x + (long)b * 512 * 4096 + p;
    float* op = out + (long)b * 512 * 4096 + p;
#pragma unroll 8
    for (int c = 0; c < 512; c++) {
        float w = __expf(Lp[(long)c * 4096] - mx) * inv;
        float xv = xp[(long)c * 4096];
        op[(long)c * 4096] = fmaf(xv, w, xv);
    }
}

// ------------------------------- launcher -----------------------------------
extern "C" void kernel_launch(void* const* d_in, const int* in_sizes, int n_in,
                              void* d_out, int out_size) {
    (void)in_sizes; (void)n_in; (void)out_size;
    const float* x  = (const float*)d_in[0];
    const float* W1 = (const float*)d_in[1];
    const float* b1 = (const float*)d_in[2];
    const float* W2 = (const float*)d_in[3];
    const float* b2 = (const float*)d_in[4];
    const float* W3 = (const float*)d_in[5];
    const float* b3 = (const float*)d_in[6];
    float* out = (float*)d_out;

    float *pAkT, *pAsp, *pAspT, *pW1T, *pW3T;
    float *pT, *pD, *pZ, *pH1, *pH2, *pL;
    unsigned *ph1, *ph2, *ph3;
    cudaGetSymbolAddress((void**)&pAkT, g_AkT);
    cudaGetSymbolAddress((void**)&pAsp, g_Asp);
    cudaGetSymbolAddress((void**)&pAspT,g_AspT);
    cudaGetSymbolAddress((void**)&pW1T, g_W1T);
    cudaGetSymbolAddress((void**)&pW3T, g_W3T);
    cudaGetSymbolAddress((void**)&pT,  g_T);
    cudaGetSymbolAddress((void**)&pD,  g_D);
    cudaGetSymbolAddress((void**)&pZ,  g_Z);
    cudaGetSymbolAddress((void**)&pH1, g_H1);
    cudaGetSymbolAddress((void**)&pH2, g_H2);
    cudaGetSymbolAddress((void**)&pL,  g_L);
    cudaGetSymbolAddress((void**)&ph1, g_hist1);
    cudaGetSymbolAddress((void**)&ph2, g_hist2);
    cudaGetSymbolAddress((void**)&ph3, g_hist3);

    k_init_dct<<<1024, 256>>>();
    k_prep_akb<<<1024, 256>>>();
    k_prep_w<<<2304, 256>>>(W1, W2, W3);

    // forward spatial DCT: T = Asp @ X @ Asp^T per (b,c) slice
    k_dct2<<<4096, 256>>>(x, pT, pAspT);

    // forward channel DCT: D[b] = Ak @ T[b]  (kept fp32: feeds threshold select)
    k_gemm<<<dim3(64, 4, 8), 256>>>(pAkT, 0, pT, 0, (long)CCH*NPIX,
                                    pD, 0, (long)CCH*NPIX,
                                    nullptr, 0, 512, 512, 1, 0);

    // transpose + bf16 convert: Dt[b][p][k]
    k_trans<<<dim3(64, 8, 8), 256>>>();

    // radix select thresholds (bit-exact kth largest of |D|)
    cudaMemsetAsync(ph1, 0, 2048 * sizeof(unsigned));
    cudaMemsetAsync(ph2, 0, 4096 * sizeof(unsigned));
    cudaMemsetAsync(ph3, 0, 4096 * sizeof(unsigned));
    k_hist1<<<2048, 256>>>();
    k_sel1<<<1, 4>>>();
    k_hist2<<<2048, 256>>>();
    k_sel2<<<1, 4>>>();
    k_hist3<<<2048, 256>>>();
    k_sel3<<<1, 4>>>();

    // masked channel inverse on tensor cores (mma.sync bf16)
    k_inv_mma<<<dim3(32, 4, 32), 256>>>();

    // inverse spatial DCT in place: Z = Asp^T @ Z @ Asp per slice
    k_dct2<<<16384, 256>>>(pZ, pZ, pAsp);

    // conv1: 1x1 512->128 + bias + relu
    k_gemm<<<dim3(64, 1, 32), 256>>>(pW1T, (long)512*128,
                                     pZ, (long)NB*CCH*NPIX, (long)CCH*NPIX,
                                     pH1, (long)NB*128*NPIX, (long)128*NPIX,
                                     b1, 128, 512, 128, 4, 1);

    // conv2: 3x3 dilation-2 128->128 + bias + relu
    k_conv2<<<dim3(64, 1, 32), 256>>>(b2);

    // conv3: 1x1 128->128 + bias + relu -> logits
    k_gemm<<<dim3(64, 1, 32), 256>>>(pW3T, (long)128*128,
                                     pH2, (long)NB*128*NPIX, (long)128*NPIX,
                                     pL, (long)128*NPIX, (long)CCH*NPIX,
                                     b3, 128, 128, 128, 4, 1);

    // softmax over 512 channels + residual gate
    k_softmax<<<dim3(32, 8), 128>>>(x, out);
}

// round 6
// speedup vs baseline: 2.3415x; 1.6450x over previous
#include <cuda_runtime.h>
#include <cuda_bf16.h>
#include <math.h>
#include <stdint.h>

#define NPIX 4096
#define CCH  512
#define NB   8
#define TOTAL 16777216
#define PI_D 3.14159265358979323846

// ----------------------------- device scratch ------------------------------
__device__ float g_Ak  [512*512];
__device__ float g_AkT [512*512];
__device__ float g_Asp [64*64];
__device__ float g_AspT[64*64];
__device__ __nv_bfloat16 g_AkTb[512*512];           // [c][k] bf16 (inverse A)
__device__ __nv_bfloat16 g_Akb [512*512];           // [k][c] bf16 (forward A)
__device__ __nv_bfloat16 g_W1b [4*128*512];         // [i][o][c]
__device__ __nv_bfloat16 g_W2b [4*9*128*128];       // [i][t][o][c]
__device__ __nv_bfloat16 g_W3b [4*128*128];         // [i][o][c]
__device__ __nv_bfloat16 g_Dt[(size_t)NB*NPIX*CCH]; // [b][p][k] bf16
__device__ float g_T [NB*CCH*NPIX];
__device__ float g_D [NB*CCH*NPIX];
__device__ float g_Z [4L*NB*CCH*NPIX];
__device__ float g_H1[4L*NB*128*NPIX];
__device__ float g_H2[4L*NB*128*NPIX];
__device__ float g_L [NB*CCH*NPIX];
__device__ unsigned g_hist1[2048];
__device__ unsigned g_hist2[4*1024];
__device__ unsigned g_hist3[4*1024];
__device__ unsigned g_selBin[8];
__device__ unsigned g_selRank[8];
__device__ unsigned g_thr[4];

__device__ __forceinline__ uint32_t smem_u32(const void* p) {
    uint32_t a;
    asm("{ .reg .u64 t; cvta.to.shared.u64 t, %1; cvt.u32.u64 %0, t; }"
        : "=r"(a) : "l"(p));
    return a;
}
__device__ __forceinline__ unsigned pack_bf2(float a, float b) {
    __nv_bfloat162 h;
    h.x = __float2bfloat16(a); h.y = __float2bfloat16(b);
    return *(unsigned*)&h;
}

// ----------------------------- init kernels --------------------------------
__global__ void k_init_dct() {
    int idx = blockIdx.x * blockDim.x + threadIdx.x;
    if (idx < 512*512) {
        int r = idx >> 9, c = idx & 511;
        double a = (double)r * ((double)c + 0.5) * (PI_D / 512.0);
        float v = (float)(cos(a) * sqrt(2.0 / 512.0));
        if (r == 0) v = (float)(cos(a) * sqrt(1.0 / 512.0));
        g_Ak [r*512 + c] = v;
        g_AkT[c*512 + r] = v;
    }
    if (idx < 64*64) {
        int r = idx >> 6, c = idx & 63;
        double a = (double)r * ((double)c + 0.5) * (PI_D / 64.0);
        float v = (float)(cos(a) * sqrt(2.0 / 64.0));
        if (r == 0) v = (float)(cos(a) * sqrt(1.0 / 64.0));
        g_Asp [r*64 + c] = v;
        g_AspT[c*64 + r] = v;
    }
}

__global__ void k_prep_b(const float* __restrict__ W1, const float* __restrict__ W2,
                         const float* __restrict__ W3) {
    int idx = blockIdx.x * blockDim.x + threadIdx.x;
    if (idx < 512*512) {
        g_AkTb[idx] = __float2bfloat16(g_AkT[idx]);
        g_Akb [idx] = __float2bfloat16(g_Ak [idx]);
    }
    if (idx < 4*128*512) g_W1b[idx] = __float2bfloat16(W1[idx]);
    if (idx < 4*128*128) g_W3b[idx] = __float2bfloat16(W3[idx]);
    if (idx < 4*128*128*9) {          // W2[i][o][c][t] -> W2b[i][t][o][c]
        int i = idx / (128*128*9); int rem = idx % (128*128*9);
        int o = rem / (128*9); rem %= (128*9);
        int c = rem / 9, t = rem % 9;
        g_W2b[((size_t)(i*9 + t)*128 + o)*128 + c] = __float2bfloat16(W2[idx]);
    }
}

// ------------------- per-slice 64x64 two-sided transform --------------------
__global__ __launch_bounds__(256) void k_dct2(const float* __restrict__ src,
                                              float* __restrict__ dst,
                                              const float* __restrict__ Amat) {
    __shared__ float sA[64][68];
    __shared__ float sX[64][68];
    int tid = threadIdx.x;
    long base = (long)blockIdx.x * 4096;
    for (int q = tid; q < 4096; q += 256) {
        sA[q >> 6][q & 63] = Amat[q];
        sX[q >> 6][q & 63] = src[base + q];
    }
    __syncthreads();

    int r0 = (tid >> 4) * 4, c0 = (tid & 15) * 4;
    float acc[4][4];
#pragma unroll
    for (int i = 0; i < 4; i++)
#pragma unroll
        for (int j = 0; j < 4; j++) acc[i][j] = 0.f;

#pragma unroll 8
    for (int m = 0; m < 64; m++) {
        float4 a = *(const float4*)&sA[m][r0];
        float4 bvec = *(const float4*)&sX[m][c0];
        float av[4] = {a.x, a.y, a.z, a.w};
        float bv[4] = {bvec.x, bvec.y, bvec.z, bvec.w};
#pragma unroll
        for (int i = 0; i < 4; i++)
#pragma unroll
            for (int j = 0; j < 4; j++) acc[i][j] = fmaf(av[i], bv[j], acc[i][j]);
    }
    __syncthreads();
#pragma unroll
    for (int i = 0; i < 4; i++)
#pragma unroll
        for (int j = 0; j < 4; j++) sX[c0 + j][r0 + i] = acc[i][j];
    __syncthreads();

#pragma unroll
    for (int i = 0; i < 4; i++)
#pragma unroll
        for (int j = 0; j < 4; j++) acc[i][j] = 0.f;
#pragma unroll 8
    for (int n = 0; n < 64; n++) {
        float4 a = *(const float4*)&sX[n][r0];
        float4 bvec = *(const float4*)&sA[n][c0];
        float av[4] = {a.x, a.y, a.z, a.w};
        float bv[4] = {bvec.x, bvec.y, bvec.z, bvec.w};
#pragma unroll
        for (int i = 0; i < 4; i++)
#pragma unroll
            for (int j = 0; j < 4; j++) acc[i][j] = fmaf(av[i], bv[j], acc[i][j]);
    }
#pragma unroll
    for (int i = 0; i < 4; i++) {
        float4 o = make_float4(acc[i][0], acc[i][1], acc[i][2], acc[i][3]);
        *(float4*)&dst[base + (r0 + i)*64 + c0] = o;
    }
}

// ------------- unified tensor-core GEMM/conv (bf16 mma.sync) ----------------
// C[m0+o][p] = relu?( bias[o] + sum_{t,k} A[i][t][o][k] * B[i,b][k][pix(p,t)] )
// A bf16 [o][k] k-contig; B fp32 [k][p]; B fragments via ldmatrix.trans.
#define LDA 72
#define LDBB 136

__global__ __launch_bounds__(256, 2) void k_cmma(
    const __nv_bfloat16* __restrict__ Abase, long aI, long tapStride, int Ktap, int ntap,
    const float* __restrict__ Bbase, long bI, long bB,
    float* __restrict__ Cbase, long cI, long cB,
    const float* __restrict__ bias, int relu, int NI)
{
    __shared__ __nv_bfloat16 sA[128 * LDA];
    __shared__ __nv_bfloat16 sB[64 * LDBB];
    int tid = threadIdx.x, wid = tid >> 5, lane = tid & 31;
    int z = blockIdx.z;
    int b = z / NI, i = z % NI;
    int p0 = blockIdx.x * 128;
    int m0 = blockIdx.y * 128;
    const __nv_bfloat16* A = Abase + (size_t)i * aI;
    const float* B = Bbase + (size_t)i * bI + (size_t)b * bB;
    float* C = Cbase + (size_t)i * cI + (size_t)b * cB;

    int wm = wid & 1, wn = wid >> 1;
    float acc[4][4][4];
#pragma unroll
    for (int mi = 0; mi < 4; mi++)
#pragma unroll
        for (int ni = 0; ni < 4; ni++)
#pragma unroll
            for (int q = 0; q < 4; q++) acc[mi][ni][q] = 0.f;

    uint32_t aAddr[4], bAddr[4];
#pragma unroll
    for (int mi = 0; mi < 4; mi++) {
        int row = wm * 64 + mi * 16 + (lane & 15);
        int col = (lane >> 4) << 3;
        aAddr[mi] = smem_u32(&sA[row * LDA + col]);
    }
#pragma unroll
    for (int ni = 0; ni < 4; ni++)
        bAddr[ni] = smem_u32(&sB[(lane & 15) * LDBB + wn * 32 + ni * 8]);

    for (int t = 0; t < ntap; t++) {
        int dy2 = (ntap == 9) ? (t / 3 - 1) * 2 : 0;
        int dx2 = (ntap == 9) ? (t % 3 - 1) * 2 : 0;
        const __nv_bfloat16* At = A + (size_t)t * tapStride;
        for (int kc = 0; kc < Ktap; kc += 64) {
            __syncthreads();
            // stage A 128x64
#pragma unroll
            for (int ps = 0; ps < 4; ps++) {
                int idx = ps * 256 + tid;
                int row = idx >> 3, slot = idx & 7;
                *(uint4*)&sA[row * LDA + slot * 8] =
                    *(const uint4*)&At[(size_t)(m0 + row) * Ktap + kc + slot * 8];
            }
            // stage B 64x128 (fp32 -> bf16, with tap shift + boundary zeros)
#pragma unroll
            for (int g4 = 0; g4 < 4; g4++) {
                int g = g4 * 256 + tid;            // 0..1023
                int krow = g >> 4, seg = g & 15;   // 8-px segment
                int p = p0 + seg * 8;
                int m = p >> 6, n = p & 63;
                int mm = m + dy2;
                bool rowok = (unsigned)mm < 64u;
                const float* src = B + (size_t)(kc + krow) * 4096 + mm * 64;
                unsigned pk[4];
                int nlo = n + dx2;
                if (rowok && nlo >= 0 && (n + 7 + dx2) < 64) {
#pragma unroll
                    for (int jj = 0; jj < 4; jj++) {
                        float2 f = *(const float2*)&src[nlo + jj * 2];
                        pk[jj] = pack_bf2(f.x, f.y);
                    }
                } else {
#pragma unroll
                    for (int jj = 0; jj < 4; jj++) {
                        float f0 = 0.f, f1 = 0.f;
                        int n0e = n + jj * 2 + dx2, n1e = n0e + 1;
                        if (rowok && (unsigned)n0e < 64u) f0 = src[n0e];
                        if (rowok && (unsigned)n1e < 64u) f1 = src[n1e];
                        pk[jj] = pack_bf2(f0, f1);
                    }
                }
                *(uint4*)&sB[krow * LDBB + seg * 8] = make_uint4(pk[0], pk[1], pk[2], pk[3]);
            }
            __syncthreads();

#pragma unroll
            for (int ks = 0; ks < 4; ks++) {
                uint32_t af[4][4], bf[4][2];
#pragma unroll
                for (int mi = 0; mi < 4; mi++) {
                    asm volatile(
                        "ldmatrix.sync.aligned.m8n8.x4.shared.b16 {%0,%1,%2,%3}, [%4];"
                        : "=r"(af[mi][0]), "=r"(af[mi][1]), "=r"(af[mi][2]), "=r"(af[mi][3])
                        : "r"(aAddr[mi] + ks * 32));
                }
#pragma unroll
                for (int ni = 0; ni < 4; ni++) {
                    asm volatile(
                        "ldmatrix.sync.aligned.m8n8.x2.trans.shared.b16 {%0,%1}, [%2];"
                        : "=r"(bf[ni][0]), "=r"(bf[ni][1])
                        : "r"(bAddr[ni] + ks * 16 * LDBB * 2));
                }
#pragma unroll
                for (int mi = 0; mi < 4; mi++)
#pragma unroll
                    for (int ni = 0; ni < 4; ni++) {
                        asm volatile(
                            "mma.sync.aligned.m16n8k16.row.col.f32.bf16.bf16.f32 "
                            "{%0,%1,%2,%3}, {%4,%5,%6,%7}, {%8,%9}, {%0,%1,%2,%3};"
                            : "+f"(acc[mi][ni][0]), "+f"(acc[mi][ni][1]),
                              "+f"(acc[mi][ni][2]), "+f"(acc[mi][ni][3])
                            : "r"(af[mi][0]), "r"(af[mi][1]), "r"(af[mi][2]), "r"(af[mi][3]),
                              "r"(bf[ni][0]), "r"(bf[ni][1]));
                    }
            }
        }
    }

    int gq = lane >> 2, tq = lane & 3;
#pragma unroll
    for (int mi = 0; mi < 4; mi++) {
        int ol = wm * 64 + mi * 16 + gq;
        float bv0 = bias ? bias[i * 128 + ol] : 0.f;
        float bv1 = bias ? bias[i * 128 + ol + 8] : 0.f;
#pragma unroll
        for (int ni = 0; ni < 4; ni++) {
            int col = p0 + wn * 32 + ni * 8 + tq * 2;
            float2 v0 = make_float2(acc[mi][ni][0] + bv0, acc[mi][ni][1] + bv0);
            float2 v1 = make_float2(acc[mi][ni][2] + bv1, acc[mi][ni][3] + bv1);
            if (relu) {
                v0.x = fmaxf(v0.x, 0.f); v0.y = fmaxf(v0.y, 0.f);
                v1.x = fmaxf(v1.x, 0.f); v1.y = fmaxf(v1.y, 0.f);
            }
            *(float2*)&C[(size_t)(m0 + ol) * 4096 + col] = v0;
            *(float2*)&C[(size_t)(m0 + ol + 8) * 4096 + col] = v1;
        }
    }
}

// -------------------- transpose D [k][p] -> Dt bf16 [p][k] ------------------
__global__ __launch_bounds__(256) void k_trans() {
    __shared__ float st[64][65];
    int p0 = blockIdx.x * 64, k0 = blockIdx.y * 64, b = blockIdx.z;
    const float* D = g_D + (size_t)b * CCH * NPIX;
    int tid = threadIdx.x;
#pragma unroll
    for (int ps = 0; ps < 16; ps++) {
        int idx = ps * 256 + tid;
        int r = idx >> 6, c = idx & 63;
        st[r][c] = D[(size_t)(k0 + r) * 4096 + p0 + c];
    }
    __syncthreads();
    __nv_bfloat16* Dt = g_Dt + (size_t)b * NPIX * CCH;
#pragma unroll
    for (int ps = 0; ps < 8; ps++) {
        int idx = ps * 256 + tid;
        int rr = idx >> 5, cc = idx & 31;
        __nv_bfloat162 v;
        v.x = __float2bfloat16(st[2*cc][rr]);
        v.y = __float2bfloat16(st[2*cc + 1][rr]);
        *(__nv_bfloat162*)&Dt[(size_t)(p0 + rr) * 512 + k0 + 2*cc] = v;
    }
}

// ------------- masked channel inverse via mma.sync (bf16 HMMA) --------------
#define LDB 72

__device__ __forceinline__ unsigned mask2(unsigned w, unsigned thrb) {
    unsigned lo = w & 0x7FFFu, hi = (w >> 16) & 0x7FFFu;
    unsigned r = w;
    if (lo < thrb) r &= 0xFFFF0000u;
    if (hi < thrb) r &= 0x0000FFFFu;
    return r;
}

__global__ __launch_bounds__(256, 2) void k_inv_mma() {
    __shared__ __nv_bfloat16 sA[128 * LDB];
    __shared__ __nv_bfloat16 sB[128 * LDB];
    int tid = threadIdx.x, wid = tid >> 5, lane = tid & 31;
    int z = blockIdx.z;
    int b = z >> 2, i = z & 3;
    int c0 = blockIdx.y * 128, n0 = blockIdx.x * 128;
    unsigned thr = g_thr[i];
    unsigned thrb = (thr + 0x7FFFu + ((thr >> 16) & 1u)) >> 16;

    const uint4* Ag = (const uint4*)g_AkTb;
    const uint4* Bg = (const uint4*)(g_Dt + (size_t)b * NPIX * CCH);

    int wm = wid & 1;
    int wn = wid >> 1;

    float acc[4][4][4];
#pragma unroll
    for (int mi = 0; mi < 4; mi++)
#pragma unroll
        for (int ni = 0; ni < 4; ni++)
#pragma unroll
            for (int q = 0; q < 4; q++) acc[mi][ni][q] = 0.f;

    uint32_t aAddr[4], bAddr[4];
#pragma unroll
    for (int mi = 0; mi < 4; mi++) {
        int row = wm * 64 + mi * 16 + (lane & 15);
        int col = (lane >> 4) << 3;
        aAddr[mi] = smem_u32(&sA[row * LDB + col]);
    }
#pragma unroll
    for (int ni = 0; ni < 4; ni++) {
        int row = wn * 32 + ni * 8 + (lane & 7);
        int col = ((lane >> 3) & 1) << 3;
        bAddr[ni] = smem_u32(&sB[row * LDB + col]);
    }

    for (int ch = 0; ch < 8; ch++) {
        int k0 = ch * 64;
        uint4 av[4], bv[4];
#pragma unroll
        for (int ps = 0; ps < 4; ps++) {
            int idx = ps * 256 + tid;
            int row = idx >> 3, slot = idx & 7;
            av[ps] = Ag[(((size_t)(c0 + row) * 512 + k0) >> 3) + slot];
            bv[ps] = Bg[(((size_t)(n0 + row) * 512 + k0) >> 3) + slot];
            bv[ps].x = mask2(bv[ps].x, thrb);
            bv[ps].y = mask2(bv[ps].y, thrb);
            bv[ps].z = mask2(bv[ps].z, thrb);
            bv[ps].w = mask2(bv[ps].w, thrb);
        }
        __syncthreads();
#pragma unroll
        for (int ps = 0; ps < 4; ps++) {
            int idx = ps * 256 + tid;
            int row = idx >> 3, slot = idx & 7;
            *(uint4*)&sA[row * LDB + slot * 8] = av[ps];
            *(uint4*)&sB[row * LDB + slot * 8] = bv[ps];
        }
        __syncthreads();

#pragma unroll
        for (int ks = 0; ks < 4; ks++) {
            uint32_t af[4][4], bf[4][2];
#pragma unroll
            for (int mi = 0; mi < 4; mi++) {
                asm volatile(
                    "ldmatrix.sync.aligned.m8n8.x4.shared.b16 {%0,%1,%2,%3}, [%4];"
                    : "=r"(af[mi][0]), "=r"(af[mi][1]), "=r"(af[mi][2]), "=r"(af[mi][3])
                    : "r"(aAddr[mi] + ks * 32));
            }
#pragma unroll
            for (int ni = 0; ni < 4; ni++) {
                asm volatile(
                    "ldmatrix.sync.aligned.m8n8.x2.shared.b16 {%0,%1}, [%2];"
                    : "=r"(bf[ni][0]), "=r"(bf[ni][1])
                    : "r"(bAddr[ni] + ks * 32));
            }
#pragma unroll
            for (int mi = 0; mi < 4; mi++)
#pragma unroll
                for (int ni = 0; ni < 4; ni++) {
                    asm volatile(
                        "mma.sync.aligned.m16n8k16.row.col.f32.bf16.bf16.f32 "
                        "{%0,%1,%2,%3}, {%4,%5,%6,%7}, {%8,%9}, {%0,%1,%2,%3};"
                        : "+f"(acc[mi][ni][0]), "+f"(acc[mi][ni][1]),
                          "+f"(acc[mi][ni][2]), "+f"(acc[mi][ni][3])
                        : "r"(af[mi][0]), "r"(af[mi][1]), "r"(af[mi][2]), "r"(af[mi][3]),
                          "r"(bf[ni][0]), "r"(bf[ni][1]));
                }
        }
    }

    float* C = g_Z + ((size_t)i * NB + b) * CCH * NPIX;
    int gq = lane >> 2, tq = lane & 3;
#pragma unroll
    for (int mi = 0; mi < 4; mi++) {
        int row = c0 + wm * 64 + mi * 16 + gq;
#pragma unroll
        for (int ni = 0; ni < 4; ni++) {
            int col = n0 + wn * 32 + ni * 8 + tq * 2;
            *(float2*)&C[(size_t)row * 4096 + col] =
                make_float2(acc[mi][ni][0], acc[mi][ni][1]);
            *(float2*)&C[(size_t)(row + 8) * 4096 + col] =
                make_float2(acc[mi][ni][2], acc[mi][ni][3]);
        }
    }
}

// --------------------------- radix select -----------------------------------
__global__ void k_hist1() {
    __shared__ unsigned sh[2048];
    for (int q = threadIdx.x; q < 2048; q += 256) sh[q] = 0;
    __syncthreads();
    const float4* D4 = (const float4*)g_D;
    int n4 = TOTAL / 4;
    for (long idx = (long)blockIdx.x * blockDim.x + threadIdx.x; idx < n4;
         idx += (long)gridDim.x * blockDim.x) {
        float4 v = D4[idx];
        atomicAdd(&sh[__float_as_uint(fabsf(v.x)) >> 20], 1u);
        atomicAdd(&sh[__float_as_uint(fabsf(v.y)) >> 20], 1u);
        atomicAdd(&sh[__float_as_uint(fabsf(v.z)) >> 20], 1u);
        atomicAdd(&sh[__float_as_uint(fabsf(v.w)) >> 20], 1u);
    }
    __syncthreads();
    for (int q = threadIdx.x; q < 2048; q += 256)
        if (sh[q]) atomicAdd(&g_hist1[q], sh[q]);
}

__global__ void k_sel1() {
    int i = threadIdx.x;
    if (i >= 4) return;
    unsigned k = (unsigned)(TOTAL >> (2 * (i + 1)));
    unsigned cum = 0;
    for (int bin = 2047; bin >= 0; bin--) {
        unsigned c = g_hist1[bin];
        if (cum + c >= k) { g_selBin[i] = (unsigned)bin; g_selRank[i] = k - cum; return; }
        cum += c;
    }
    g_selBin[i] = 0; g_selRank[i] = 1;
}

__global__ void k_hist2() {
    __shared__ unsigned sh[4096];
    for (int q = threadIdx.x; q < 4096; q += 256) sh[q] = 0;
    __syncthreads();
    unsigned s0 = g_selBin[0], s1 = g_selBin[1], s2 = g_selBin[2], s3 = g_selBin[3];
    const float4* D4 = (const float4*)g_D;
    int n4 = TOTAL / 4;
    for (long idx = (long)blockIdx.x * blockDim.x + threadIdx.x; idx < n4;
         idx += (long)gridDim.x * blockDim.x) {
        float4 v = D4[idx];
        float comps[4] = {v.x, v.y, v.z, v.w};
#pragma unroll
        for (int j = 0; j < 4; j++) {
            unsigned u = __float_as_uint(fabsf(comps[j]));
            unsigned hi = u >> 20, sub = (u >> 10) & 1023;
            if (hi == s0) atomicAdd(&sh[sub], 1u);
            if (hi == s1) atomicAdd(&sh[1024 + sub], 1u);
            if (hi == s2) atomicAdd(&sh[2048 + sub], 1u);
            if (hi == s3) atomicAdd(&sh[3072 + sub], 1u);
        }
    }
    __syncthreads();
    for (int q = threadIdx.x; q < 4096; q += 256)
        if (sh[q]) atomicAdd(&g_hist2[q], sh[q]);
}

__global__ void k_sel2() {
    int i = threadIdx.x;
    if (i >= 4) return;
    unsigned k = g_selRank[i];
    unsigned cum = 0;
    for (int bin = 1023; bin >= 0; bin--) {
        unsigned c = g_hist2[i * 1024 + bin];
        if (cum + c >= k) { g_selBin[4 + i] = (unsigned)bin; g_selRank[4 + i] = k - cum; return; }
        cum += c;
    }
    g_selBin[4 + i] = 0; g_selRank[4 + i] = 1;
}

__global__ void k_hist3() {
    __shared__ unsigned sh[4096];
    for (int q = threadIdx.x; q < 4096; q += 256) sh[q] = 0;
    __syncthreads();
    unsigned t0 = (g_selBin[0] << 10) | g_selBin[4];
    unsigned t1 = (g_selBin[1] << 10) | g_selBin[5];
    unsigned t2 = (g_selBin[2] << 10) | g_selBin[6];
    unsigned t3 = (g_selBin[3] << 10) | g_selBin[7];
    const float4* D4 = (const float4*)g_D;
    int n4 = TOTAL / 4;
    for (long idx = (long)blockIdx.x * blockDim.x + threadIdx.x; idx < n4;
         idx += (long)gridDim.x * blockDim.x) {
        float4 v = D4[idx];
        float comps[4] = {v.x, v.y, v.z, v.w};
#pragma unroll
        for (int j = 0; j < 4; j++) {
            unsigned u = __float_as_uint(fabsf(comps[j]));
            unsigned hi = u >> 10, lo = u & 1023;
            if (hi == t0) atomicAdd(&sh[lo], 1u);
            if (hi == t1) atomicAdd(&sh[1024 + lo], 1u);
            if (hi == t2) atomicAdd(&sh[2048 + lo], 1u);
            if (hi == t3) atomicAdd(&sh[3072 + lo], 1u);
        }
    }
    __syncthreads();
    for (int q = threadIdx.x; q < 4096; q += 256)
        if (sh[q]) atomicAdd(&g_hist3[q], sh[q]);
}

__global__ void k_sel3() {
    int i = threadIdx.x;
    if (i >= 4) return;
    unsigned k = g_selRank[4 + i];
    unsigned cum = 0;
    for (int bin = 1023; bin >= 0; bin--) {
        unsigned c = g_hist3[i * 1024 + bin];
        if (cum + c >= k) {
            g_thr[i] = (g_selBin[i] << 20) | (g_selBin[4 + i] << 10) | (unsigned)bin;
            return;
        }
        cum += c;
    }
    g_thr[i] = (g_selBin[i] << 20) | (g_selBin[4 + i] << 10);
}

// ------------------------- softmax + residual gate --------------------------
__global__ __launch_bounds__(128) void k_softmax(const float* __restrict__ x,
                                                 float* __restrict__ out) {
    int b = blockIdx.y;
    int p = blockIdx.x * 128 + threadIdx.x;
    const float* Lp = g_L + (long)b * 512 * 4096 + p;
    float mx = 0.f;
#pragma unroll 8
    for (int c = 0; c < 512; c++) mx = fmaxf(mx, Lp[(long)c * 4096]);
    float s = 0.f;
#pragma unroll 8
    for (int c = 0; c < 512; c++) s += __expf(Lp[(long)c * 4096] - mx);
    float inv = 1.f / s;
    const float* xp = x + (long)b * 512 * 4096 + p;
    float* op = out + (long)b * 512 * 4096 + p;
#pragma unroll 8
    for (int c = 0; c < 512; c++) {
        float w = __expf(Lp[(long)c * 4096] - mx) * inv;
        float xv = xp[(long)c * 4096];
        op[(long)c * 4096] = fmaf(xv, w, xv);
    }
}

// ------------------------------- launcher -----------------------------------
extern "C" void kernel_launch(void* const* d_in, const int* in_sizes, int n_in,
                              void* d_out, int out_size) {
    (void)in_sizes; (void)n_in; (void)out_size;
    const float* x  = (const float*)d_in[0];
    const float* W1 = (const float*)d_in[1];
    const float* b1 = (const float*)d_in[2];
    const float* W2 = (const float*)d_in[3];
    const float* b2 = (const float*)d_in[4];
    const float* W3 = (const float*)d_in[5];
    const float* b3 = (const float*)d_in[6];
    float* out = (float*)d_out;

    float *pAsp, *pAspT, *pT, *pD, *pZ, *pH1, *pH2, *pL;
    __nv_bfloat16 *pAkb, *pW1b, *pW2b, *pW3b;
    unsigned *ph1, *ph2, *ph3;
    cudaGetSymbolAddress((void**)&pAsp, g_Asp);
    cudaGetSymbolAddress((void**)&pAspT,g_AspT);
    cudaGetSymbolAddress((void**)&pAkb, g_Akb);
    cudaGetSymbolAddress((void**)&pW1b, g_W1b);
    cudaGetSymbolAddress((void**)&pW2b, g_W2b);
    cudaGetSymbolAddress((void**)&pW3b, g_W3b);
    cudaGetSymbolAddress((void**)&pT,  g_T);
    cudaGetSymbolAddress((void**)&pD,  g_D);
    cudaGetSymbolAddress((void**)&pZ,  g_Z);
    cudaGetSymbolAddress((void**)&pH1, g_H1);
    cudaGetSymbolAddress((void**)&pH2, g_H2);
    cudaGetSymbolAddress((void**)&pL,  g_L);
    cudaGetSymbolAddress((void**)&ph1, g_hist1);
    cudaGetSymbolAddress((void**)&ph2, g_hist2);
    cudaGetSymbolAddress((void**)&ph3, g_hist3);

    k_init_dct<<<1024, 256>>>();
    k_prep_b<<<2304, 256>>>(W1, W2, W3);

    // forward spatial DCT: T = Asp @ X @ Asp^T per (b,c) slice
    k_dct2<<<4096, 256>>>(x, pT, pAspT);

    // forward channel DCT on tensor cores: D[b] = Ak @ T[b]
    k_cmma<<<dim3(32, 4, 8), 256>>>(pAkb, 0, 0, 512, 1,
                                    pT, 0, 512L*4096,
                                    pD, 0, 512L*4096,
                                    nullptr, 0, 1);

    // transpose + bf16 convert: Dt[b][p][k]
    k_trans<<<dim3(64, 8, 8), 256>>>();

    // radix select thresholds (bit-exact kth largest of |D|)
    cudaMemsetAsync(ph1, 0, 2048 * sizeof(unsigned));
    cudaMemsetAsync(ph2, 0, 4096 * sizeof(unsigned));
    cudaMemsetAsync(ph3, 0, 4096 * sizeof(unsigned));
    k_hist1<<<2048, 256>>>();
    k_sel1<<<1, 4>>>();
    k_hist2<<<2048, 256>>>();
    k_sel2<<<1, 4>>>();
    k_hist3<<<2048, 256>>>();
    k_sel3<<<1, 4>>>();

    // masked channel inverse on tensor cores
    k_inv_mma<<<dim3(32, 4, 32), 256>>>();

    // inverse spatial DCT in place: Z = Asp^T @ Z @ Asp per slice
    k_dct2<<<16384, 256>>>(pZ, pZ, pAsp);

    // conv1: 1x1 512->128 + bias + relu (tensor cores)
    k_cmma<<<dim3(32, 1, 32), 256>>>(pW1b, 512L*128, 0, 512, 1,
                                     pZ, 8L*512*4096, 512L*4096,
                                     pH1, 8L*128*4096, 128L*4096,
                                     b1, 1, 4);

    // conv2: 3x3 dil-2 128->128 + bias + relu (tensor cores, 9 taps)
    k_cmma<<<dim3(32, 1, 32), 256>>>(pW2b, 9L*128*128, 128L*128, 128, 9,
                                     pH1, 8L*128*4096, 128L*4096,
                                     pH2, 8L*128*4096, 128L*4096,
                                     b2, 1, 4);

    // conv3: 1x1 128->128 + bias + relu -> logits (tensor cores)
    k_cmma<<<dim3(32, 1, 32), 256>>>(pW3b, 128L*128, 0, 128, 1,
                                     pH2, 8L*128*4096, 128L*4096,
                                     pL, 128L*4096, 512L*4096,
                                     b3, 1, 4);

    // softmax over 512 channels + residual gate
    k_softmax<<<dim3(32, 8), 128>>>(x, out);
}

// round 7
// speedup vs baseline: 3.0210x; 1.2902x over previous
#include <cuda_runtime.h>
#include <cuda_bf16.h>
#include <math.h>
#include <stdint.h>

#define NPIX 4096
#define CCH  512
#define NB   8
#define TOTAL 16777216
#define PI_D 3.14159265358979323846

// ----------------------------- device scratch ------------------------------
__device__ float g_Ak  [512*512];
__device__ float g_AkT [512*512];
__device__ float g_Asp [64*64];
__device__ float g_AspT[64*64];
__device__ __nv_bfloat16 g_AkTb[512*512];           // [c][k] bf16 (inverse A)
__device__ __nv_bfloat16 g_Akb [512*512];           // [k][c] bf16 (forward A)
__device__ __nv_bfloat16 g_Aspb [64*64];            // Asp bf16
__device__ __nv_bfloat16 g_AspTb[64*64];            // AspT bf16
__device__ __nv_bfloat16 g_W1b [4*128*512];         // [i][o][c]
__device__ __nv_bfloat16 g_W2b [4*9*128*128];       // [i][t][o][c]
__device__ __nv_bfloat16 g_W3b [4*128*128];         // [i][o][c]
__device__ __nv_bfloat16 g_Dt[(size_t)NB*NPIX*CCH]; // [b][p][k] bf16
__device__ float g_T [NB*CCH*NPIX];
__device__ float g_D [NB*CCH*NPIX];
__device__ float g_Z [4L*NB*CCH*NPIX];
__device__ float g_H1[4L*NB*128*NPIX];
__device__ float g_H2[4L*NB*128*NPIX];
__device__ float g_L [NB*CCH*NPIX];
__device__ unsigned g_hist1[2048];
__device__ unsigned g_hist2[4*1024];
__device__ unsigned g_hist3[4*1024];
__device__ unsigned g_selBin[8];
__device__ unsigned g_selRank[8];
__device__ unsigned g_thr[4];

__device__ __forceinline__ uint32_t smem_u32(const void* p) {
    uint32_t a;
    asm("{ .reg .u64 t; cvta.to.shared.u64 t, %1; cvt.u32.u64 %0, t; }"
        : "=r"(a) : "l"(p));
    return a;
}
__device__ __forceinline__ unsigned pack_bf2(float a, float b) {
    __nv_bfloat162 h;
    h.x = __float2bfloat16(a); h.y = __float2bfloat16(b);
    return *(unsigned*)&h;
}

// ----------------------------- init kernels --------------------------------
__global__ void k_init_dct() {
    int idx = blockIdx.x * blockDim.x + threadIdx.x;
    if (idx < 512*512) {
        int r = idx >> 9, c = idx & 511;
        double a = (double)r * ((double)c + 0.5) * (PI_D / 512.0);
        float v = (float)(cos(a) * sqrt(2.0 / 512.0));
        if (r == 0) v = (float)(cos(a) * sqrt(1.0 / 512.0));
        g_Ak [r*512 + c] = v;
        g_AkT[c*512 + r] = v;
    }
    if (idx < 64*64) {
        int r = idx >> 6, c = idx & 63;
        double a = (double)r * ((double)c + 0.5) * (PI_D / 64.0);
        float v = (float)(cos(a) * sqrt(2.0 / 64.0));
        if (r == 0) v = (float)(cos(a) * sqrt(1.0 / 64.0));
        g_Asp [r*64 + c] = v;
        g_AspT[c*64 + r] = v;
    }
}

__global__ void k_prep_b(const float* __restrict__ W1, const float* __restrict__ W2,
                         const float* __restrict__ W3) {
    int idx = blockIdx.x * blockDim.x + threadIdx.x;
    if (idx < 512*512) {
        g_AkTb[idx] = __float2bfloat16(g_AkT[idx]);
        g_Akb [idx] = __float2bfloat16(g_Ak [idx]);
    }
    if (idx < 64*64) {
        g_Aspb [idx] = __float2bfloat16(g_Asp [idx]);
        g_AspTb[idx] = __float2bfloat16(g_AspT[idx]);
    }
    if (idx < 4*128*512) g_W1b[idx] = __float2bfloat16(W1[idx]);
    if (idx < 4*128*128) g_W3b[idx] = __float2bfloat16(W3[idx]);
    if (idx < 4*128*128*9) {          // W2[i][o][c][t] -> W2b[i][t][o][c]
        int i = idx / (128*128*9); int rem = idx % (128*128*9);
        int o = rem / (128*9); rem %= (128*9);
        int c = rem / 9, t = rem % 9;
        g_W2b[((size_t)(i*9 + t)*128 + o)*128 + c] = __float2bfloat16(W2[idx]);
    }
}

// ------------- spatial 64x64 two-sided transform on tensor cores ------------
// Y = Mt @ (X @ Mt^T): fwd Mt=Asp, inv Mt=AspT. 4 slices/CTA, 2 warps/slice.
#define SLD 72

__global__ __launch_bounds__(256) void k_sdct(const float* __restrict__ src,
                                              float* __restrict__ dst,
                                              const __nv_bfloat16* __restrict__ Mt) {
    __shared__ __nv_bfloat16 sM[64 * SLD];
    __shared__ __nv_bfloat16 sX[4 * 64 * SLD];
    int tid = threadIdx.x, wid = tid >> 5, lane = tid & 31;
    size_t base = (size_t)blockIdx.x * 4 * 4096;

    // load Mt (4096 bf16)
    for (int g = tid; g < 2048; g += 256) {
        int row = g >> 5, c2 = g & 31;
        *(__nv_bfloat162*)&sM[row * SLD + c2 * 2] =
            *(const __nv_bfloat162*)&Mt[row * 64 + c2 * 2];
    }
    // load 4 slices of X (fp32 -> bf16)
    for (int g = tid; g < 8192; g += 256) {
        int s = g >> 11;
        int r = (g >> 5) & 63;
        int c2 = g & 31;
        float2 f = *(const float2*)&src[base + (size_t)s * 4096 + r * 64 + c2 * 2];
        *(unsigned*)&sX[s * 64 * SLD + r * SLD + c2 * 2] = pack_bf2(f.x, f.y);
    }
    __syncthreads();

    int s = wid >> 1, band = (wid & 1) * 32;
    __nv_bfloat16* Xs = &sX[s * 64 * SLD];
    int gq = lane >> 2, tq = lane & 3;

    // ---- phase 1: C1[m][j] = sum_n X[m][n] * Mt[j][n] ----
    uint32_t aAddr[2], bAddr[8];
#pragma unroll
    for (int mi = 0; mi < 2; mi++)
        aAddr[mi] = smem_u32(&Xs[(band + mi * 16 + (lane & 15)) * SLD + ((lane >> 4) << 3)]);
#pragma unroll
    for (int ni = 0; ni < 8; ni++)
        bAddr[ni] = smem_u32(&sM[(ni * 8 + (lane & 7)) * SLD + (((lane >> 3) & 1) << 3)]);

    float acc[2][8][4];
#pragma unroll
    for (int mi = 0; mi < 2; mi++)
#pragma unroll
        for (int ni = 0; ni < 8; ni++)
#pragma unroll
            for (int q = 0; q < 4; q++) acc[mi][ni][q] = 0.f;

#pragma unroll
    for (int ks = 0; ks < 4; ks++) {
        uint32_t af[2][4], bf[8][2];
#pragma unroll
        for (int mi = 0; mi < 2; mi++)
            asm volatile("ldmatrix.sync.aligned.m8n8.x4.shared.b16 {%0,%1,%2,%3}, [%4];"
                : "=r"(af[mi][0]), "=r"(af[mi][1]), "=r"(af[mi][2]), "=r"(af[mi][3])
                : "r"(aAddr[mi] + ks * 32));
#pragma unroll
        for (int ni = 0; ni < 8; ni++)
            asm volatile("ldmatrix.sync.aligned.m8n8.x2.shared.b16 {%0,%1}, [%2];"
                : "=r"(bf[ni][0]), "=r"(bf[ni][1]) : "r"(bAddr[ni] + ks * 32));
#pragma unroll
        for (int mi = 0; mi < 2; mi++)
#pragma unroll
            for (int ni = 0; ni < 8; ni++)
                asm volatile(
                    "mma.sync.aligned.m16n8k16.row.col.f32.bf16.bf16.f32 "
                    "{%0,%1,%2,%3}, {%4,%5,%6,%7}, {%8,%9}, {%0,%1,%2,%3};"
                    : "+f"(acc[mi][ni][0]), "+f"(acc[mi][ni][1]),
                      "+f"(acc[mi][ni][2]), "+f"(acc[mi][ni][3])
                    : "r"(af[mi][0]), "r"(af[mi][1]), "r"(af[mi][2]), "r"(af[mi][3]),
                      "r"(bf[ni][0]), "r"(bf[ni][1]));
    }
    __syncthreads();   // all warps done READING X before overwrite

    // store C1 transposed (bf16) back into Xs: C1T[j][m]
#pragma unroll
    for (int mi = 0; mi < 2; mi++) {
        int m = band + mi * 16 + gq;
#pragma unroll
        for (int ni = 0; ni < 8; ni++) {
            int j0 = ni * 8 + tq * 2;
            Xs[j0 * SLD + m]           = __float2bfloat16(acc[mi][ni][0]);
            Xs[(j0 + 1) * SLD + m]     = __float2bfloat16(acc[mi][ni][1]);
            Xs[j0 * SLD + m + 8]       = __float2bfloat16(acc[mi][ni][2]);
            Xs[(j0 + 1) * SLD + m + 8] = __float2bfloat16(acc[mi][ni][3]);
        }
    }
    __syncthreads();

    // ---- phase 2: C2[i][j] = sum_m Mt[i][m] * C1T[j][m] ----
    uint32_t aAddr2[2], bAddr2[8];
#pragma unroll
    for (int mi = 0; mi < 2; mi++)
        aAddr2[mi] = smem_u32(&sM[(band + mi * 16 + (lane & 15)) * SLD + ((lane >> 4) << 3)]);
#pragma unroll
    for (int ni = 0; ni < 8; ni++)
        bAddr2[ni] = smem_u32(&Xs[(ni * 8 + (lane & 7)) * SLD + (((lane >> 3) & 1) << 3)]);

#pragma unroll
    for (int mi = 0; mi < 2; mi++)
#pragma unroll
        for (int ni = 0; ni < 8; ni++)
#pragma unroll
            for (int q = 0; q < 4; q++) acc[mi][ni][q] = 0.f;

#pragma unroll
    for (int ks = 0; ks < 4; ks++) {
        uint32_t af[2][4], bf[8][2];
#pragma unroll
        for (int mi = 0; mi < 2; mi++)
            asm volatile("ldmatrix.sync.aligned.m8n8.x4.shared.b16 {%0,%1,%2,%3}, [%4];"
                : "=r"(af[mi][0]), "=r"(af[mi][1]), "=r"(af[mi][2]), "=r"(af[mi][3])
                : "r"(aAddr2[mi] + ks * 32));
#pragma unroll
        for (int ni = 0; ni < 8; ni++)
            asm volatile("ldmatrix.sync.aligned.m8n8.x2.shared.b16 {%0,%1}, [%2];"
                : "=r"(bf[ni][0]), "=r"(bf[ni][1]) : "r"(bAddr2[ni] + ks * 32));
#pragma unroll
        for (int mi = 0; mi < 2; mi++)
#pragma unroll
            for (int ni = 0; ni < 8; ni++)
                asm volatile(
                    "mma.sync.aligned.m16n8k16.row.col.f32.bf16.bf16.f32 "
                    "{%0,%1,%2,%3}, {%4,%5,%6,%7}, {%8,%9}, {%0,%1,%2,%3};"
                    : "+f"(acc[mi][ni][0]), "+f"(acc[mi][ni][1]),
                      "+f"(acc[mi][ni][2]), "+f"(acc[mi][ni][3])
                    : "r"(af[mi][0]), "r"(af[mi][1]), "r"(af[mi][2]), "r"(af[mi][3]),
                      "r"(bf[ni][0]), "r"(bf[ni][1]));
    }

    // store C2 fp32
    float* D = dst + base + (size_t)s * 4096;
#pragma unroll
    for (int mi = 0; mi < 2; mi++) {
        int i = band + mi * 16 + gq;
#pragma unroll
        for (int ni = 0; ni < 8; ni++) {
            int j = ni * 8 + tq * 2;
            *(float2*)&D[i * 64 + j] = make_float2(acc[mi][ni][0], acc[mi][ni][1]);
            *(float2*)&D[(i + 8) * 64 + j] = make_float2(acc[mi][ni][2], acc[mi][ni][3]);
        }
    }
}

// ------------- unified tensor-core GEMM/conv (bf16 mma.sync) ----------------
#define LDA 72
#define LDBB 136

__global__ __launch_bounds__(256, 2) void k_cmma(
    const __nv_bfloat16* __restrict__ Abase, long aI, long tapStride, int Ktap, int ntap,
    const float* __restrict__ Bbase, long bI, long bB,
    float* __restrict__ Cbase, long cI, long cB,
    const float* __restrict__ bias, int relu, int NI)
{
    __shared__ __nv_bfloat16 sA[128 * LDA];
    __shared__ __nv_bfloat16 sB[64 * LDBB];
    int tid = threadIdx.x, wid = tid >> 5, lane = tid & 31;
    int z = blockIdx.z;
    int b = z / NI, i = z % NI;
    int p0 = blockIdx.x * 128;
    int m0 = blockIdx.y * 128;
    const __nv_bfloat16* A = Abase + (size_t)i * aI;
    const float* B = Bbase + (size_t)i * bI + (size_t)b * bB;
    float* C = Cbase + (size_t)i * cI + (size_t)b * cB;

    int wm = wid & 1, wn = wid >> 1;
    float acc[4][4][4];
#pragma unroll
    for (int mi = 0; mi < 4; mi++)
#pragma unroll
        for (int ni = 0; ni < 4; ni++)
#pragma unroll
            for (int q = 0; q < 4; q++) acc[mi][ni][q] = 0.f;

    uint32_t aAddr[4], bAddr[4];
#pragma unroll
    for (int mi = 0; mi < 4; mi++) {
        int row = wm * 64 + mi * 16 + (lane & 15);
        int col = (lane >> 4) << 3;
        aAddr[mi] = smem_u32(&sA[row * LDA + col]);
    }
#pragma unroll
    for (int ni = 0; ni < 4; ni++)
        bAddr[ni] = smem_u32(&sB[(lane & 15) * LDBB + wn * 32 + ni * 8]);

    for (int t = 0; t < ntap; t++) {
        int dy2 = (ntap == 9) ? (t / 3 - 1) * 2 : 0;
        int dx2 = (ntap == 9) ? (t % 3 - 1) * 2 : 0;
        const __nv_bfloat16* At = A + (size_t)t * tapStride;
        for (int kc = 0; kc < Ktap; kc += 64) {
            __syncthreads();
#pragma unroll
            for (int ps = 0; ps < 4; ps++) {
                int idx = ps * 256 + tid;
                int row = idx >> 3, slot = idx & 7;
                *(uint4*)&sA[row * LDA + slot * 8] =
                    *(const uint4*)&At[(size_t)(m0 + row) * Ktap + kc + slot * 8];
            }
#pragma unroll
            for (int g4 = 0; g4 < 4; g4++) {
                int g = g4 * 256 + tid;
                int krow = g >> 4, seg = g & 15;
                int p = p0 + seg * 8;
                int m = p >> 6, n = p & 63;
                int mm = m + dy2;
                bool rowok = (unsigned)mm < 64u;
                const float* src = B + (size_t)(kc + krow) * 4096 + mm * 64;
                unsigned pk[4];
                int nlo = n + dx2;
                if (rowok && nlo >= 0 && (n + 7 + dx2) < 64) {
#pragma unroll
                    for (int jj = 0; jj < 4; jj++) {
                        float2 f = *(const float2*)&src[nlo + jj * 2];
                        pk[jj] = pack_bf2(f.x, f.y);
                    }
                } else {
#pragma unroll
                    for (int jj = 0; jj < 4; jj++) {
                        float f0 = 0.f, f1 = 0.f;
                        int n0e = n + jj * 2 + dx2, n1e = n0e + 1;
                        if (rowok && (unsigned)n0e < 64u) f0 = src[n0e];
                        if (rowok && (unsigned)n1e < 64u) f1 = src[n1e];
                        pk[jj] = pack_bf2(f0, f1);
                    }
                }
                *(uint4*)&sB[krow * LDBB + seg * 8] = make_uint4(pk[0], pk[1], pk[2], pk[3]);
            }
            __syncthreads();

#pragma unroll
            for (int ks = 0; ks < 4; ks++) {
                uint32_t af[4][4], bf[4][2];
#pragma unroll
                for (int mi = 0; mi < 4; mi++) {
                    asm volatile(
                        "ldmatrix.sync.aligned.m8n8.x4.shared.b16 {%0,%1,%2,%3}, [%4];"
                        : "=r"(af[mi][0]), "=r"(af[mi][1]), "=r"(af[mi][2]), "=r"(af[mi][3])
                        : "r"(aAddr[mi] + ks * 32));
                }
#pragma unroll
                for (int ni = 0; ni < 4; ni++) {
                    asm volatile(
                        "ldmatrix.sync.aligned.m8n8.x2.trans.shared.b16 {%0,%1}, [%2];"
                        : "=r"(bf[ni][0]), "=r"(bf[ni][1])
                        : "r"(bAddr[ni] + ks * 16 * LDBB * 2));
                }
#pragma unroll
                for (int mi = 0; mi < 4; mi++)
#pragma unroll
                    for (int ni = 0; ni < 4; ni++) {
                        asm volatile(
                            "mma.sync.aligned.m16n8k16.row.col.f32.bf16.bf16.f32 "
                            "{%0,%1,%2,%3}, {%4,%5,%6,%7}, {%8,%9}, {%0,%1,%2,%3};"
                            : "+f"(acc[mi][ni][0]), "+f"(acc[mi][ni][1]),
                              "+f"(acc[mi][ni][2]), "+f"(acc[mi][ni][3])
                            : "r"(af[mi][0]), "r"(af[mi][1]), "r"(af[mi][2]), "r"(af[mi][3]),
                              "r"(bf[ni][0]), "r"(bf[ni][1]));
                    }
            }
        }
    }

    int gq = lane >> 2, tq = lane & 3;
#pragma unroll
    for (int mi = 0; mi < 4; mi++) {
        int ol = wm * 64 + mi * 16 + gq;
        float bv0 = bias ? bias[i * 128 + ol] : 0.f;
        float bv1 = bias ? bias[i * 128 + ol + 8] : 0.f;
#pragma unroll
        for (int ni = 0; ni < 4; ni++) {
            int col = p0 + wn * 32 + ni * 8 + tq * 2;
            float2 v0 = make_float2(acc[mi][ni][0] + bv0, acc[mi][ni][1] + bv0);
            float2 v1 = make_float2(acc[mi][ni][2] + bv1, acc[mi][ni][3] + bv1);
            if (relu) {
                v0.x = fmaxf(v0.x, 0.f); v0.y = fmaxf(v0.y, 0.f);
                v1.x = fmaxf(v1.x, 0.f); v1.y = fmaxf(v1.y, 0.f);
            }
            *(float2*)&C[(size_t)(m0 + ol) * 4096 + col] = v0;
            *(float2*)&C[(size_t)(m0 + ol + 8) * 4096 + col] = v1;
        }
    }
}

// -------------------- transpose D [k][p] -> Dt bf16 [p][k] ------------------
__global__ __launch_bounds__(256) void k_trans() {
    __shared__ float st[64][65];
    int p0 = blockIdx.x * 64, k0 = blockIdx.y * 64, b = blockIdx.z;
    const float* D = g_D + (size_t)b * CCH * NPIX;
    int tid = threadIdx.x;
#pragma unroll
    for (int ps = 0; ps < 16; ps++) {
        int idx = ps * 256 + tid;
        int r = idx >> 6, c = idx & 63;
        st[r][c] = D[(size_t)(k0 + r) * 4096 + p0 + c];
    }
    __syncthreads();
    __nv_bfloat16* Dt = g_Dt + (size_t)b * NPIX * CCH;
#pragma unroll
    for (int ps = 0; ps < 8; ps++) {
        int idx = ps * 256 + tid;
        int rr = idx >> 5, cc = idx & 31;
        __nv_bfloat162 v;
        v.x = __float2bfloat16(st[2*cc][rr]);
        v.y = __float2bfloat16(st[2*cc + 1][rr]);
        *(__nv_bfloat162*)&Dt[(size_t)(p0 + rr) * 512 + k0 + 2*cc] = v;
    }
}

// ------------- masked channel inverse via mma.sync (bf16 HMMA) --------------
#define LDB 72

__device__ __forceinline__ unsigned mask2(unsigned w, unsigned thrb) {
    unsigned lo = w & 0x7FFFu, hi = (w >> 16) & 0x7FFFu;
    unsigned r = w;
    if (lo < thrb) r &= 0xFFFF0000u;
    if (hi < thrb) r &= 0x0000FFFFu;
    return r;
}

__global__ __launch_bounds__(256, 2) void k_inv_mma() {
    __shared__ __nv_bfloat16 sA[128 * LDB];
    __shared__ __nv_bfloat16 sB[128 * LDB];
    int tid = threadIdx.x, wid = tid >> 5, lane = tid & 31;
    int z = blockIdx.z;
    int b = z >> 2, i = z & 3;
    int c0 = blockIdx.y * 128, n0 = blockIdx.x * 128;
    unsigned thr = g_thr[i];
    unsigned thrb = (thr + 0x7FFFu + ((thr >> 16) & 1u)) >> 16;

    const uint4* Ag = (const uint4*)g_AkTb;
    const uint4* Bg = (const uint4*)(g_Dt + (size_t)b * NPIX * CCH);

    int wm = wid & 1;
    int wn = wid >> 1;

    float acc[4][4][4];
#pragma unroll
    for (int mi = 0; mi < 4; mi++)
#pragma unroll
        for (int ni = 0; ni < 4; ni++)
#pragma unroll
            for (int q = 0; q < 4; q++) acc[mi][ni][q] = 0.f;

    uint32_t aAddr[4], bAddr[4];
#pragma unroll
    for (int mi = 0; mi < 4; mi++) {
        int row = wm * 64 + mi * 16 + (lane & 15);
        int col = (lane >> 4) << 3;
        aAddr[mi] = smem_u32(&sA[row * LDB + col]);
    }
#pragma unroll
    for (int ni = 0; ni < 4; ni++) {
        int row = wn * 32 + ni * 8 + (lane & 7);
        int col = ((lane >> 3) & 1) << 3;
        bAddr[ni] = smem_u32(&sB[row * LDB + col]);
    }

    for (int ch = 0; ch < 8; ch++) {
        int k0 = ch * 64;
        uint4 av[4], bv[4];
#pragma unroll
        for (int ps = 0; ps < 4; ps++) {
            int idx = ps * 256 + tid;
            int row = idx >> 3, slot = idx & 7;
            av[ps] = Ag[(((size_t)(c0 + row) * 512 + k0) >> 3) + slot];
            bv[ps] = Bg[(((size_t)(n0 + row) * 512 + k0) >> 3) + slot];
            bv[ps].x = mask2(bv[ps].x, thrb);
            bv[ps].y = mask2(bv[ps].y, thrb);
            bv[ps].z = mask2(bv[ps].z, thrb);
            bv[ps].w = mask2(bv[ps].w, thrb);
        }
        __syncthreads();
#pragma unroll
        for (int ps = 0; ps < 4; ps++) {
            int idx = ps * 256 + tid;
            int row = idx >> 3, slot = idx & 7;
            *(uint4*)&sA[row * LDB + slot * 8] = av[ps];
            *(uint4*)&sB[row * LDB + slot * 8] = bv[ps];
        }
        __syncthreads();

#pragma unroll
        for (int ks = 0; ks < 4; ks++) {
            uint32_t af[4][4], bf[4][2];
#pragma unroll
            for (int mi = 0; mi < 4; mi++) {
                asm volatile(
                    "ldmatrix.sync.aligned.m8n8.x4.shared.b16 {%0,%1,%2,%3}, [%4];"
                    : "=r"(af[mi][0]), "=r"(af[mi][1]), "=r"(af[mi][2]), "=r"(af[mi][3])
                    : "r"(aAddr[mi] + ks * 32));
            }
#pragma unroll
            for (int ni = 0; ni < 4; ni++) {
                asm volatile(
                    "ldmatrix.sync.aligned.m8n8.x2.shared.b16 {%0,%1}, [%2];"
                    : "=r"(bf[ni][0]), "=r"(bf[ni][1])
                    : "r"(bAddr[ni] + ks * 32));
            }
#pragma unroll
            for (int mi = 0; mi < 4; mi++)
#pragma unroll
                for (int ni = 0; ni < 4; ni++) {
                    asm volatile(
                        "mma.sync.aligned.m16n8k16.row.col.f32.bf16.bf16.f32 "
                        "{%0,%1,%2,%3}, {%4,%5,%6,%7}, {%8,%9}, {%0,%1,%2,%3};"
                        : "+f"(acc[mi][ni][0]), "+f"(acc[mi][ni][1]),
                          "+f"(acc[mi][ni][2]), "+f"(acc[mi][ni][3])
                        : "r"(af[mi][0]), "r"(af[mi][1]), "r"(af[mi][2]), "r"(af[mi][3]),
                          "r"(bf[ni][0]), "r"(bf[ni][1]));
                }
        }
    }

    float* C = g_Z + ((size_t)i * NB + b) * CCH * NPIX;
    int gq = lane >> 2, tq = lane & 3;
#pragma unroll
    for (int mi = 0; mi < 4; mi++) {
        int row = c0 + wm * 64 + mi * 16 + gq;
#pragma unroll
        for (int ni = 0; ni < 4; ni++) {
            int col = n0 + wn * 32 + ni * 8 + tq * 2;
            *(float2*)&C[(size_t)row * 4096 + col] =
                make_float2(acc[mi][ni][0], acc[mi][ni][1]);
            *(float2*)&C[(size_t)(row + 8) * 4096 + col] =
                make_float2(acc[mi][ni][2], acc[mi][ni][3]);
        }
    }
}

// --------------------------- radix select -----------------------------------
__global__ void k_hist1() {
    __shared__ unsigned sh[2048];
    for (int q = threadIdx.x; q < 2048; q += 256) sh[q] = 0;
    __syncthreads();
    const float4* D4 = (const float4*)g_D;
    int n4 = TOTAL / 4;
    for (long idx = (long)blockIdx.x * blockDim.x + threadIdx.x; idx < n4;
         idx += (long)gridDim.x * blockDim.x) {
        float4 v = D4[idx];
        atomicAdd(&sh[__float_as_uint(fabsf(v.x)) >> 20], 1u);
        atomicAdd(&sh[__float_as_uint(fabsf(v.y)) >> 20], 1u);
        atomicAdd(&sh[__float_as_uint(fabsf(v.z)) >> 20], 1u);
        atomicAdd(&sh[__float_as_uint(fabsf(v.w)) >> 20], 1u);
    }
    __syncthreads();
    for (int q = threadIdx.x; q < 2048; q += 256)
        if (sh[q]) atomicAdd(&g_hist1[q], sh[q]);
}

__global__ void k_sel1() {
    int i = threadIdx.x;
    if (i >= 4) return;
    unsigned k = (unsigned)(TOTAL >> (2 * (i + 1)));
    unsigned cum = 0;
    for (int bin = 2047; bin >= 0; bin--) {
        unsigned c = g_hist1[bin];
        if (cum + c >= k) { g_selBin[i] = (unsigned)bin; g_selRank[i] = k - cum; return; }
        cum += c;
    }
    g_selBin[i] = 0; g_selRank[i] = 1;
}

__global__ void k_hist2() {
    __shared__ unsigned sh[4096];
    for (int q = threadIdx.x; q < 4096; q += 256) sh[q] = 0;
    __syncthreads();
    unsigned s0 = g_selBin[0], s1 = g_selBin[1], s2 = g_selBin[2], s3 = g_selBin[3];
    const float4* D4 = (const float4*)g_D;
    int n4 = TOTAL / 4;
    for (long idx = (long)blockIdx.x * blockDim.x + threadIdx.x; idx < n4;
         idx += (long)gridDim.x * blockDim.x) {
        float4 v = D4[idx];
        float comps[4] = {v.x, v.y, v.z, v.w};
#pragma unroll
        for (int j = 0; j < 4; j++) {
            unsigned u = __float_as_uint(fabsf(comps[j]));
            unsigned hi = u >> 20, sub = (u >> 10) & 1023;
            if (hi == s0) atomicAdd(&sh[sub], 1u);
            if (hi == s1) atomicAdd(&sh[1024 + sub], 1u);
            if (hi == s2) atomicAdd(&sh[2048 + sub], 1u);
            if (hi == s3) atomicAdd(&sh[3072 + sub], 1u);
        }
    }
    __syncthreads();
    for (int q = threadIdx.x; q < 4096; q += 256)
        if (sh[q]) atomicAdd(&g_hist2[q], sh[q]);
}

__global__ void k_sel2() {
    int i = threadIdx.x;
    if (i >= 4) return;
    unsigned k = g_selRank[i];
    unsigned cum = 0;
    for (int bin = 1023; bin >= 0; bin--) {
        unsigned c = g_hist2[i * 1024 + bin];
        if (cum + c >= k) { g_selBin[4 + i] = (unsigned)bin; g_selRank[4 + i] = k - cum; return; }
        cum += c;
    }
    g_selBin[4 + i] = 0; g_selRank[4 + i] = 1;
}

__global__ void k_hist3() {
    __shared__ unsigned sh[4096];
    for (int q = threadIdx.x; q < 4096; q += 256) sh[q] = 0;
    __syncthreads();
    unsigned t0 = (g_selBin[0] << 10) | g_selBin[4];
    unsigned t1 = (g_selBin[1] << 10) | g_selBin[5];
    unsigned t2 = (g_selBin[2] << 10) | g_selBin[6];
    unsigned t3 = (g_selBin[3] << 10) | g_selBin[7];
    const float4* D4 = (const float4*)g_D;
    int n4 = TOTAL / 4;
    for (long idx = (long)blockIdx.x * blockDim.x + threadIdx.x; idx < n4;
         idx += (long)gridDim.x * blockDim.x) {
        float4 v = D4[idx];
        float comps[4] = {v.x, v.y, v.z, v.w};
#pragma unroll
        for (int j = 0; j < 4; j++) {
            unsigned u = __float_as_uint(fabsf(comps[j]));
            unsigned hi = u >> 10, lo = u & 1023;
            if (hi == t0) atomicAdd(&sh[lo], 1u);
            if (hi == t1) atomicAdd(&sh[1024 + lo], 1u);
            if (hi == t2) atomicAdd(&sh[2048 + lo], 1u);
            if (hi == t3) atomicAdd(&sh[3072 + lo], 1u);
        }
    }
    __syncthreads();
    for (int q = threadIdx.x; q < 4096; q += 256)
        if (sh[q]) atomicAdd(&g_hist3[q], sh[q]);
}

__global__ void k_sel3() {
    int i = threadIdx.x;
    if (i >= 4) return;
    unsigned k = g_selRank[4 + i];
    unsigned cum = 0;
    for (int bin = 1023; bin >= 0; bin--) {
        unsigned c = g_hist3[i * 1024 + bin];
        if (cum + c >= k) {
            g_thr[i] = (g_selBin[i] << 20) | (g_selBin[4 + i] << 10) | (unsigned)bin;
            return;
        }
        cum += c;
    }
    g_thr[i] = (g_selBin[i] << 20) | (g_selBin[4 + i] << 10);
}

// ------------------------- softmax + residual gate --------------------------
__global__ __launch_bounds__(128) void k_softmax(const float* __restrict__ x,
                                                 float* __restrict__ out) {
    int b = blockIdx.y;
    int p = blockIdx.x * 128 + threadIdx.x;
    const float* Lp = g_L + (long)b * 512 * 4096 + p;
    float mx = 0.f;
#pragma unroll 8
    for (int c = 0; c < 512; c++) mx = fmaxf(mx, Lp[(long)c * 4096]);
    float s = 0.f;
#pragma unroll 8
    for (int c = 0; c < 512; c++) s += __expf(Lp[(long)c * 4096] - mx);
    float inv = 1.f / s;
    const float* xp = x + (long)b * 512 * 4096 + p;
    float* op = out + (long)b * 512 * 4096 + p;
#pragma unroll 8
    for (int c = 0; c < 512; c++) {
        float w = __expf(Lp[(long)c * 4096] - mx) * inv;
        float xv = xp[(long)c * 4096];
        op[(long)c * 4096] = fmaf(xv, w, xv);
    }
}

// ------------------------------- launcher -----------------------------------
extern "C" void kernel_launch(void* const* d_in, const int* in_sizes, int n_in,
                              void* d_out, int out_size) {
    (void)in_sizes; (void)n_in; (void)out_size;
    const float* x  = (const float*)d_in[0];
    const float* W1 = (const float*)d_in[1];
    const float* b1 = (const float*)d_in[2];
    const float* W2 = (const float*)d_in[3];
    const float* b2 = (const float*)d_in[4];
    const float* W3 = (const float*)d_in[5];
    const float* b3 = (const float*)d_in[6];
    float* out = (float*)d_out;

    float *pT, *pD, *pZ, *pH1, *pH2, *pL;
    __nv_bfloat16 *pAkb, *pW1b, *pW2b, *pW3b, *pAspb, *pAspTb;
    unsigned *ph1, *ph2, *ph3;
    cudaGetSymbolAddress((void**)&pAkb, g_Akb);
    cudaGetSymbolAddress((void**)&pAspb, g_Aspb);
    cudaGetSymbolAddress((void**)&pAspTb, g_AspTb);
    cudaGetSymbolAddress((void**)&pW1b, g_W1b);
    cudaGetSymbolAddress((void**)&pW2b, g_W2b);
    cudaGetSymbolAddress((void**)&pW3b, g_W3b);
    cudaGetSymbolAddress((void**)&pT,  g_T);
    cudaGetSymbolAddress((void**)&pD,  g_D);
    cudaGetSymbolAddress((void**)&pZ,  g_Z);
    cudaGetSymbolAddress((void**)&pH1, g_H1);
    cudaGetSymbolAddress((void**)&pH2, g_H2);
    cudaGetSymbolAddress((void**)&pL,  g_L);
    cudaGetSymbolAddress((void**)&ph1, g_hist1);
    cudaGetSymbolAddress((void**)&ph2, g_hist2);
    cudaGetSymbolAddress((void**)&ph3, g_hist3);

    k_init_dct<<<1024, 256>>>();
    k_prep_b<<<2304, 256>>>(W1, W2, W3);

    // forward spatial DCT on tensor cores: T = Asp @ X @ Asp^T per slice
    k_sdct<<<1024, 256>>>(x, pT, pAspb);

    // forward channel DCT on tensor cores: D[b] = Ak @ T[b]
    k_cmma<<<dim3(32, 4, 8), 256>>>(pAkb, 0, 0, 512, 1,
                                    pT, 0, 512L*4096,
                                    pD, 0, 512L*4096,
                                    nullptr, 0, 1);

    // transpose + bf16 convert: Dt[b][p][k]
    k_trans<<<dim3(64, 8, 8), 256>>>();

    // radix select thresholds (bit-exact kth largest of |D|)
    cudaMemsetAsync(ph1, 0, 2048 * sizeof(unsigned));
    cudaMemsetAsync(ph2, 0, 4096 * sizeof(unsigned));
    cudaMemsetAsync(ph3, 0, 4096 * sizeof(unsigned));
    k_hist1<<<2048, 256>>>();
    k_sel1<<<1, 4>>>();
    k_hist2<<<2048, 256>>>();
    k_sel2<<<1, 4>>>();
    k_hist3<<<2048, 256>>>();
    k_sel3<<<1, 4>>>();

    // masked channel inverse on tensor cores
    k_inv_mma<<<dim3(32, 4, 32), 256>>>();

    // inverse spatial DCT on tensor cores (in place): Z = Asp^T @ Z @ Asp
    k_sdct<<<4096, 256>>>(pZ, pZ, pAspTb);

    // conv1: 1x1 512->128 + bias + relu (tensor cores)
    k_cmma<<<dim3(32, 1, 32), 256>>>(pW1b, 512L*128, 0, 512, 1,
                                     pZ, 8L*512*4096, 512L*4096,
                                     pH1, 8L*128*4096, 128L*4096,
                                     b1, 1, 4);

    // conv2: 3x3 dil-2 128->128 + bias + relu (tensor cores, 9 taps)
    k_cmma<<<dim3(32, 1, 32), 256>>>(pW2b, 9L*128*128, 128L*128, 128, 9,
                                     pH1, 8L*128*4096, 128L*4096,
                                     pH2, 8L*128*4096, 128L*4096,
                                     b2, 1, 4);

    // conv3: 1x1 128->128 + bias + relu -> logits (tensor cores)
    k_cmma<<<dim3(32, 1, 32), 256>>>(pW3b, 128L*128, 0, 128, 1,
                                     pH2, 8L*128*4096, 128L*4096,
                                     pL, 128L*4096, 512L*4096,
                                     b3, 1, 4);

    // softmax over 512 channels + residual gate
    k_softmax<<<dim3(32, 8), 128>>>(x, out);
}